// round 1
// baseline (speedup 1.0000x reference)
#include <cuda_runtime.h>
#include <math.h>

// Problem constants
#define BATCH 2
#define SEQ   2048
#define HID   1024
#define NH    16
#define DH    64

// Tiling
#define BQ 64
#define BK 64
#define STR 68           // smem row stride (floats), 16B-aligned, avoids worst conflicts

// ctx scratch: [B, L, H] fp32 = 16 MB
__device__ float g_ctx[(size_t)BATCH * SEQ * HID];

// ---------------------------------------------------------------------------
// Kernel 1: flash-style self-attention per (b, h, q-tile).
// x is [B, L, H]; head slice is x[b, :, h*64 : h*64+64]. Q = K = V = slice.
// Block: 256 threads as 16x16 (ty, tx); each thread owns a 4x4 microtile.
// ---------------------------------------------------------------------------
__global__ __launch_bounds__(256, 1) void attn_kernel(const float* __restrict__ x) {
    extern __shared__ float sm[];
    float* Qs = sm;                 // [BQ][STR]
    float* Ks = sm + BQ * STR;      // [BK][STR]  (also serves as V tile)
    float* Ps = sm + 2 * BQ * STR;  // [BQ][STR]  (exp probs)

    const int tid = threadIdx.x;
    const int ty = tid >> 4;        // 0..15
    const int tx = tid & 15;        // 0..15
    const int qt = blockIdx.x;      // 0..31
    const int h  = blockIdx.y;      // 0..15
    const int b  = blockIdx.z;      // 0..1

    const float* xb = x + (size_t)b * SEQ * HID + h * DH;
    const int q0 = qt * BQ;

    // Load Q tile [64 x 64] (coalesced float4)
    {
        const int r = tid >> 4;
        const int c = (tid & 15) * 4;
        #pragma unroll
        for (int rr = 0; rr < BQ; rr += 16) {
            float4 v = *(const float4*)(xb + (size_t)(q0 + rr + r) * HID + c);
            *(float4*)&Qs[(rr + r) * STR + c] = v;
        }
    }

    float m[4], l[4], acc[4][4];
    #pragma unroll
    for (int i = 0; i < 4; i++) {
        m[i] = -1e30f;
        l[i] = 0.0f;
        #pragma unroll
        for (int j = 0; j < 4; j++) acc[i][j] = 0.0f;
    }

    const float scale = 0.125f;  // 1/sqrt(64)

    for (int kt = 0; kt < SEQ / BK; kt++) {
        __syncthreads();  // previous iteration's reads of Ks are done
        // Load K tile (== V tile)
        {
            const int r = tid >> 4;
            const int c = (tid & 15) * 4;
            #pragma unroll
            for (int rr = 0; rr < BK; rr += 16) {
                float4 v = *(const float4*)(xb + (size_t)(kt * BK + rr + r) * HID + c);
                *(float4*)&Ks[(rr + r) * STR + c] = v;
            }
        }
        __syncthreads();

        // S = Q K^T  (4x4 per thread, float4 over the dh dimension)
        float s[4][4];
        #pragma unroll
        for (int i = 0; i < 4; i++)
            #pragma unroll
            for (int j = 0; j < 4; j++) s[i][j] = 0.0f;

        #pragma unroll
        for (int kk = 0; kk < DH; kk += 4) {
            float4 qv[4], kv[4];
            #pragma unroll
            for (int i = 0; i < 4; i++)
                qv[i] = *(const float4*)&Qs[(ty * 4 + i) * STR + kk];
            #pragma unroll
            for (int j = 0; j < 4; j++)
                kv[j] = *(const float4*)&Ks[(tx * 4 + j) * STR + kk];
            #pragma unroll
            for (int i = 0; i < 4; i++)
                #pragma unroll
                for (int j = 0; j < 4; j++)
                    s[i][j] += qv[i].x * kv[j].x + qv[i].y * kv[j].y +
                               qv[i].z * kv[j].z + qv[i].w * kv[j].w;
        }

        // Online softmax (row stats across the 16-lane tx group via shuffles)
        #pragma unroll
        for (int i = 0; i < 4; i++) {
            float sv0 = s[i][0] * scale;
            float sv1 = s[i][1] * scale;
            float sv2 = s[i][2] * scale;
            float sv3 = s[i][3] * scale;
            float mx = fmaxf(fmaxf(sv0, sv1), fmaxf(sv2, sv3));
            #pragma unroll
            for (int off = 1; off < 16; off <<= 1)
                mx = fmaxf(mx, __shfl_xor_sync(0xffffffffu, mx, off));
            float mn = fmaxf(m[i], mx);
            float corr = __expf(m[i] - mn);
            float p0 = __expf(sv0 - mn);
            float p1 = __expf(sv1 - mn);
            float p2 = __expf(sv2 - mn);
            float p3 = __expf(sv3 - mn);
            float rs = p0 + p1 + p2 + p3;
            #pragma unroll
            for (int off = 1; off < 16; off <<= 1)
                rs += __shfl_xor_sync(0xffffffffu, rs, off);
            l[i] = l[i] * corr + rs;
            m[i] = mn;
            #pragma unroll
            for (int j = 0; j < 4; j++) acc[i][j] *= corr;
            *(float4*)&Ps[(ty * 4 + i) * STR + tx * 4] = make_float4(p0, p1, p2, p3);
        }
        __syncwarp();  // Ps rows for this ty group are produced within this warp

        // O += P @ V   (V tile == Ks tile)
        #pragma unroll
        for (int k0 = 0; k0 < BK; k0 += 4) {
            float pk[4][4];  // pk[i][kk]
            #pragma unroll
            for (int i = 0; i < 4; i++) {
                float4 pv = *(const float4*)&Ps[(ty * 4 + i) * STR + k0];
                pk[i][0] = pv.x; pk[i][1] = pv.y; pk[i][2] = pv.z; pk[i][3] = pv.w;
            }
            float kb[4][4];  // kb[kk][j]
            #pragma unroll
            for (int kk = 0; kk < 4; kk++) {
                float4 vv = *(const float4*)&Ks[(k0 + kk) * STR + tx * 4];
                kb[kk][0] = vv.x; kb[kk][1] = vv.y; kb[kk][2] = vv.z; kb[kk][3] = vv.w;
            }
            #pragma unroll
            for (int i = 0; i < 4; i++)
                #pragma unroll
                for (int j = 0; j < 4; j++)
                    #pragma unroll
                    for (int kk = 0; kk < 4; kk++)
                        acc[i][j] += pk[i][kk] * kb[kk][j];
        }
    }

    // Normalize and store ctx (back to [B, L, H] layout)
    #pragma unroll
    for (int i = 0; i < 4; i++) {
        float inv = 1.0f / l[i];
        float4 o = make_float4(acc[i][0] * inv, acc[i][1] * inv,
                               acc[i][2] * inv, acc[i][3] * inv);
        *(float4*)&g_ctx[((size_t)b * SEQ + q0 + ty * 4 + i) * HID + h * DH + tx * 4] = o;
    }
}

// ---------------------------------------------------------------------------
// Kernel 2: out[n][j] = sum_k ctx[n][k] * W[j][k] + bias[j]
// M = B*L = 4096, N = H = 1024, K = H = 1024. Both operands K-contiguous.
// ---------------------------------------------------------------------------
__global__ __launch_bounds__(256, 2) void proj_kernel(const float* __restrict__ W,
                                                      const float* __restrict__ bias,
                                                      float* __restrict__ out) {
    __shared__ float As[64 * STR];
    __shared__ float Bs[64 * STR];

    const int tid = threadIdx.x;
    const int ty = tid >> 4;
    const int tx = tid & 15;
    const int j0 = blockIdx.x * 64;
    const int n0 = blockIdx.y * 64;

    float s[4][4];
    #pragma unroll
    for (int i = 0; i < 4; i++)
        #pragma unroll
        for (int j = 0; j < 4; j++) s[i][j] = 0.0f;

    for (int k0 = 0; k0 < HID; k0 += 64) {
        __syncthreads();
        {
            const int r = tid >> 4;
            const int c = (tid & 15) * 4;
            #pragma unroll
            for (int rr = 0; rr < 64; rr += 16) {
                *(float4*)&As[(rr + r) * STR + c] =
                    *(const float4*)&g_ctx[(size_t)(n0 + rr + r) * HID + k0 + c];
                *(float4*)&Bs[(rr + r) * STR + c] =
                    *(const float4*)&W[(size_t)(j0 + rr + r) * HID + k0 + c];
            }
        }
        __syncthreads();

        #pragma unroll
        for (int kk = 0; kk < 64; kk += 4) {
            float4 av[4], bv[4];
            #pragma unroll
            for (int i = 0; i < 4; i++)
                av[i] = *(const float4*)&As[(ty * 4 + i) * STR + kk];
            #pragma unroll
            for (int j = 0; j < 4; j++)
                bv[j] = *(const float4*)&Bs[(tx * 4 + j) * STR + kk];
            #pragma unroll
            for (int i = 0; i < 4; i++)
                #pragma unroll
                for (int j = 0; j < 4; j++)
                    s[i][j] += av[i].x * bv[j].x + av[i].y * bv[j].y +
                               av[i].z * bv[j].z + av[i].w * bv[j].w;
        }
    }

    float4 bb = *(const float4*)&bias[j0 + tx * 4];
    #pragma unroll
    for (int i = 0; i < 4; i++) {
        float4 o = make_float4(s[i][0] + bb.x, s[i][1] + bb.y,
                               s[i][2] + bb.z, s[i][3] + bb.w);
        *(float4*)&out[(size_t)(n0 + ty * 4 + i) * HID + j0 + tx * 4] = o;
    }
}

// ---------------------------------------------------------------------------
extern "C" void kernel_launch(void* const* d_in, const int* in_sizes, int n_in,
                              void* d_out, int out_size) {
    const float* x    = (const float*)d_in[0];  // key [B, L, H]
    const float* W    = (const float*)d_in[1];  // W_ctx [H, H]
    const float* bias = (const float*)d_in[2];  // b_ctx [H]
    float* out = (float*)d_out;

    const int smem_bytes = 3 * BQ * STR * (int)sizeof(float);  // 52224
    cudaFuncSetAttribute(attn_kernel, cudaFuncAttributeMaxDynamicSharedMemorySize,
                         smem_bytes);

    dim3 grid1(SEQ / BQ, NH, BATCH);   // (32, 16, 2)
    attn_kernel<<<grid1, 256, smem_bytes>>>(x);

    dim3 grid2(HID / 64, (BATCH * SEQ) / 64);  // (16, 64)
    proj_kernel<<<grid2, 256>>>(W, bias, out);
}

// round 3
// speedup vs baseline: 4.6005x; 4.6005x over previous
#include <cuda_runtime.h>
#include <cuda_fp16.h>
#include <stdint.h>

#define BATCH 2
#define SEQ   2048
#define HID   1024
#define NH    16
#define DH    64
#define BQ    128
#define BK    64

// fp16 hi/lo splits in global scratch
__device__ __half g_xh[(size_t)BATCH * SEQ * HID];
__device__ __half g_xl[(size_t)BATCH * SEQ * HID];
__device__ __half g_ch[(size_t)BATCH * SEQ * HID];
__device__ __half g_cl[(size_t)BATCH * SEQ * HID];
__device__ __half g_wh[(size_t)HID * HID];
__device__ __half g_wl[(size_t)HID * HID];

// ---------------------------------------------------------------------------
__device__ __forceinline__ uint32_t smem_u32(const void* p) {
    uint32_t a;
    asm("{ .reg .u64 t; cvta.to.shared.u64 t, %1; cvt.u32.u64 %0, t; }" : "=r"(a) : "l"(p));
    return a;
}

#define SW(o) ((uint32_t)(o) ^ ((((uint32_t)(o)) >> 3) & 0x70))

__device__ __forceinline__ void ldm_x4(uint32_t& r0, uint32_t& r1, uint32_t& r2, uint32_t& r3,
                                       uint32_t addr) {
    asm volatile("ldmatrix.sync.aligned.m8n8.x4.shared.b16 {%0,%1,%2,%3}, [%4];"
                 : "=r"(r0), "=r"(r1), "=r"(r2), "=r"(r3) : "r"(addr));
}
__device__ __forceinline__ void ldm_x4t(uint32_t& r0, uint32_t& r1, uint32_t& r2, uint32_t& r3,
                                        uint32_t addr) {
    asm volatile("ldmatrix.sync.aligned.m8n8.x4.trans.shared.b16 {%0,%1,%2,%3}, [%4];"
                 : "=r"(r0), "=r"(r1), "=r"(r2), "=r"(r3) : "r"(addr));
}

__device__ __forceinline__ void mma_f16(float* c, const uint32_t* a, uint32_t b0, uint32_t b1) {
    asm volatile("mma.sync.aligned.m16n8k16.row.col.f32.f16.f16.f32 "
                 "{%0,%1,%2,%3}, {%4,%5,%6,%7}, {%8,%9}, {%0,%1,%2,%3};"
                 : "+f"(c[0]), "+f"(c[1]), "+f"(c[2]), "+f"(c[3])
                 : "r"(a[0]), "r"(a[1]), "r"(a[2]), "r"(a[3]), "r"(b0), "r"(b1));
}

__device__ __forceinline__ uint32_t packh(__half lo, __half hi) {
    return (uint32_t)__half_as_ushort(lo) | ((uint32_t)__half_as_ushort(hi) << 16);
}

// ---------------------------------------------------------------------------
__global__ void conv_x_kernel(const float* __restrict__ src, int n) {
    int i = blockIdx.x * blockDim.x + threadIdx.x;
    if (i < n) {
        float v = src[i];
        __half h = __float2half_rn(v);
        g_xh[i] = h;
        g_xl[i] = __float2half_rn(v - __half2float(h));
    }
}
__global__ void conv_w_kernel(const float* __restrict__ src, int n) {
    int i = blockIdx.x * blockDim.x + threadIdx.x;
    if (i < n) {
        float v = src[i];
        __half h = __float2half_rn(v);
        g_wh[i] = h;
        g_wl[i] = __float2half_rn(v - __half2float(h));
    }
}

// ---------------------------------------------------------------------------
// Flash attention: CTA = (q-tile 128, head, batch); 256 threads = 8 warps.
// smem: QH 0..16K, QL 16K..32K, KH 32K..40K, KL 40K..48K  (rows = 128B SW)
// ---------------------------------------------------------------------------
__global__ __launch_bounds__(256, 1) void attn_kernel() {
    extern __shared__ __align__(128) char sm[];
    const uint32_t sb = smem_u32(sm);
    const int tid = threadIdx.x, lane = tid & 31, wid = tid >> 5;
    const int qt = blockIdx.x, h = blockIdx.y, b = blockIdx.z;
    const int q0 = qt * BQ;
    const int gID = lane >> 2, tc = lane & 3;

    // Load Q tile hi/lo (128 rows x 128B each buffer)
    #pragma unroll
    for (int i = 0; i < 4; i++) {
        int e = i * 256 + tid;             // 0..1023
        int row = e >> 3, ch = e & 7;
        size_t src = ((size_t)(b * SEQ + q0 + row)) * HID + h * DH + ch * 8;
        uint32_t o = SW(row * 128 + ch * 16);
        *(uint4*)(sm + o)         = *(const uint4*)(g_xh + src);
        *(uint4*)(sm + 16384 + o) = *(const uint4*)(g_xl + src);
    }
    __syncthreads();

    // Q fragments (registers, reused across all KV tiles)
    uint32_t aQh[4][4], aQl[4][4];
    {
        int row = wid * 16 + (lane & 15);
        int chb = lane >> 4;  // 0/1
        #pragma unroll
        for (int ks = 0; ks < 4; ks++) {
            uint32_t o = SW(row * 128 + (ks * 2 + chb) * 16);
            ldm_x4(aQh[ks][0], aQh[ks][1], aQh[ks][2], aQh[ks][3], sb + o);
            ldm_x4(aQl[ks][0], aQl[ks][1], aQl[ks][2], aQl[ks][3], sb + 16384 + o);
        }
    }

    float o_[8][4];
    #pragma unroll
    for (int n = 0; n < 8; n++)
        #pragma unroll
        for (int j = 0; j < 4; j++) o_[n][j] = 0.0f;
    float m_lo = -1e30f, m_hi = -1e30f, l_lo = 0.0f, l_hi = 0.0f;

    for (int kt = 0; kt < SEQ / BK; kt++) {
        __syncthreads();
        // Load K(==V) tile hi/lo (64 rows x 128B)
        #pragma unroll
        for (int i = 0; i < 2; i++) {
            int e = i * 256 + tid;         // 0..511
            int row = e >> 3, ch = e & 7;
            size_t src = ((size_t)(b * SEQ + kt * BK + row)) * HID + h * DH + ch * 8;
            uint32_t o = SW(row * 128 + ch * 16);
            *(uint4*)(sm + 32768 + o) = *(const uint4*)(g_xh + src);
            *(uint4*)(sm + 40960 + o) = *(const uint4*)(g_xl + src);
        }
        __syncthreads();

        // ---- S = Q K^T (3-product fp16 emulation) ----
        float s[8][4];
        #pragma unroll
        for (int n = 0; n < 8; n++)
            #pragma unroll
            for (int j = 0; j < 4; j++) s[n][j] = 0.0f;

        #pragma unroll
        for (int n = 0; n < 8; n++) {
            int row = n * 8 + (lane & 7);
            #pragma unroll
            for (int p = 0; p < 2; p++) {
                uint32_t o = SW(row * 128 + (p * 4 + (lane >> 3)) * 16);
                uint32_t b0, b1, b2, b3, c0, c1, c2, c3;
                ldm_x4(b0, b1, b2, b3, sb + 32768 + o);
                ldm_x4(c0, c1, c2, c3, sb + 40960 + o);
                mma_f16(s[n], aQh[2 * p],     b0, b1);
                mma_f16(s[n], aQh[2 * p],     c0, c1);
                mma_f16(s[n], aQl[2 * p],     b0, b1);
                mma_f16(s[n], aQh[2 * p + 1], b2, b3);
                mma_f16(s[n], aQh[2 * p + 1], c2, c3);
                mma_f16(s[n], aQl[2 * p + 1], b2, b3);
            }
        }

        // ---- online softmax (rows r=gID and r+8 per thread; quad reduce) ----
        const float sc = 0.125f;
        float mlo = -1e30f, mhi = -1e30f;
        #pragma unroll
        for (int n = 0; n < 8; n++) {
            mlo = fmaxf(mlo, fmaxf(s[n][0], s[n][1]));
            mhi = fmaxf(mhi, fmaxf(s[n][2], s[n][3]));
        }
        mlo = fmaxf(mlo, __shfl_xor_sync(0xffffffffu, mlo, 1));
        mlo = fmaxf(mlo, __shfl_xor_sync(0xffffffffu, mlo, 2));
        mhi = fmaxf(mhi, __shfl_xor_sync(0xffffffffu, mhi, 1));
        mhi = fmaxf(mhi, __shfl_xor_sync(0xffffffffu, mhi, 2));
        float nml = fmaxf(m_lo, mlo * sc), nmh = fmaxf(m_hi, mhi * sc);
        float clo = __expf(m_lo - nml), chi = __expf(m_hi - nmh);
        m_lo = nml; m_hi = nmh;

        float slo = 0.0f, shi = 0.0f;
        uint32_t aPh[4][4], aPl[4][4];
        #pragma unroll
        for (int n = 0; n < 8; n++) {
            float p0 = __expf(s[n][0] * sc - nml);
            float p1 = __expf(s[n][1] * sc - nml);
            float p2 = __expf(s[n][2] * sc - nmh);
            float p3 = __expf(s[n][3] * sc - nmh);
            slo += p0 + p1;
            shi += p2 + p3;
            __half h0 = __float2half_rn(p0), h1 = __float2half_rn(p1);
            __half h2 = __float2half_rn(p2), h3 = __float2half_rn(p3);
            int t = n >> 1, idx = (n & 1) * 2;
            aPh[t][idx]     = packh(h0, h1);
            aPh[t][idx + 1] = packh(h2, h3);
            aPl[t][idx]     = packh(__float2half_rn(p0 - __half2float(h0)),
                                    __float2half_rn(p1 - __half2float(h1)));
            aPl[t][idx + 1] = packh(__float2half_rn(p2 - __half2float(h2)),
                                    __float2half_rn(p3 - __half2float(h3)));
        }
        slo += __shfl_xor_sync(0xffffffffu, slo, 1);
        slo += __shfl_xor_sync(0xffffffffu, slo, 2);
        shi += __shfl_xor_sync(0xffffffffu, shi, 1);
        shi += __shfl_xor_sync(0xffffffffu, shi, 2);
        l_lo = l_lo * clo + slo;
        l_hi = l_hi * chi + shi;
        #pragma unroll
        for (int n = 0; n < 8; n++) {
            o_[n][0] *= clo; o_[n][1] *= clo;
            o_[n][2] *= chi; o_[n][3] *= chi;
        }

        // ---- O += P V (V = K tile; B frags via ldmatrix.x4.trans) ----
        #pragma unroll
        for (int n = 0; n < 8; n++) {
            #pragma unroll
            for (int p = 0; p < 2; p++) {
                int row = p * 32 + (lane >> 3) * 8 + (lane & 7);
                uint32_t o = SW(row * 128 + n * 16);
                uint32_t v0, v1, v2, v3, w0, w1, w2, w3;
                ldm_x4t(v0, v1, v2, v3, sb + 32768 + o);
                ldm_x4t(w0, w1, w2, w3, sb + 40960 + o);
                mma_f16(o_[n], aPh[2 * p],     v0, v1);
                mma_f16(o_[n], aPh[2 * p],     w0, w1);
                mma_f16(o_[n], aPl[2 * p],     v0, v1);
                mma_f16(o_[n], aPh[2 * p + 1], v2, v3);
                mma_f16(o_[n], aPh[2 * p + 1], w2, w3);
                mma_f16(o_[n], aPl[2 * p + 1], v2, v3);
            }
        }
    }

    // ---- normalize, split to fp16 hi/lo, write ctx ----
    {
        float il = 1.0f / l_lo, ih = 1.0f / l_hi;
        size_t rlo = (size_t)(b * SEQ + q0 + wid * 16 + gID);
        size_t rhi = rlo + 8;
        #pragma unroll
        for (int n = 0; n < 8; n++) {
            int col = h * DH + n * 8 + tc * 2;
            float v0 = o_[n][0] * il, v1 = o_[n][1] * il;
            float v2 = o_[n][2] * ih, v3 = o_[n][3] * ih;
            __half h0 = __float2half_rn(v0), h1 = __float2half_rn(v1);
            __half h2 = __float2half_rn(v2), h3 = __float2half_rn(v3);
            *(uint32_t*)(g_ch + rlo * HID + col) = packh(h0, h1);
            *(uint32_t*)(g_cl + rlo * HID + col) =
                packh(__float2half_rn(v0 - __half2float(h0)),
                      __float2half_rn(v1 - __half2float(h1)));
            *(uint32_t*)(g_ch + rhi * HID + col) = packh(h2, h3);
            *(uint32_t*)(g_cl + rhi * HID + col) =
                packh(__float2half_rn(v2 - __half2float(h2)),
                      __float2half_rn(v3 - __half2float(h3)));
        }
    }
}

// ---------------------------------------------------------------------------
// Projection: out[m][n] = sum_k ctx[m][k] * W[n][k] + bias[n]
// CTA: 128x128 tile, 256 threads (8 warps, 4x2), k-chunks of 64.
// smem: AH 0, AL 16K, BH 32K, BL 48K  (64KB)
// ---------------------------------------------------------------------------
__global__ __launch_bounds__(256, 1) void proj_kernel(const float* __restrict__ bias,
                                                      float* __restrict__ out) {
    extern __shared__ __align__(128) char sm[];
    const uint32_t sb = smem_u32(sm);
    const int tid = threadIdx.x, lane = tid & 31, wid = tid >> 5;
    const int wm = wid >> 1, wn = wid & 1;
    const int n0 = blockIdx.x * 128, m0 = blockIdx.y * 128;
    const int gID = lane >> 2, tc = lane & 3;

    float acc[2][8][4];
    #pragma unroll
    for (int mt = 0; mt < 2; mt++)
        #pragma unroll
        for (int n = 0; n < 8; n++)
            #pragma unroll
            for (int j = 0; j < 4; j++) acc[mt][n][j] = 0.0f;

    for (int kc = 0; kc < HID / 64; kc++) {
        __syncthreads();
        #pragma unroll
        for (int i = 0; i < 4; i++) {
            int e = i * 256 + tid;          // 0..1023
            int row = e >> 3, ch = e & 7;
            size_t ao = ((size_t)(m0 + row)) * HID + kc * 64 + ch * 8;
            size_t bo = ((size_t)(n0 + row)) * HID + kc * 64 + ch * 8;
            uint32_t o = SW(row * 128 + ch * 16);
            *(uint4*)(sm + o)         = *(const uint4*)(g_ch + ao);
            *(uint4*)(sm + 16384 + o) = *(const uint4*)(g_cl + ao);
            *(uint4*)(sm + 32768 + o) = *(const uint4*)(g_wh + bo);
            *(uint4*)(sm + 49152 + o) = *(const uint4*)(g_wl + bo);
        }
        __syncthreads();

        #pragma unroll
        for (int p = 0; p < 2; p++) {
            uint32_t aH[2][2][4], aL[2][2][4];  // [ks parity][mtile][4]
            #pragma unroll
            for (int kk = 0; kk < 2; kk++) {
                int ks = 2 * p + kk;
                #pragma unroll
                for (int mt = 0; mt < 2; mt++) {
                    int row = wm * 32 + mt * 16 + (lane & 15);
                    uint32_t o = SW(row * 128 + (ks * 2 + (lane >> 4)) * 16);
                    ldm_x4(aH[kk][mt][0], aH[kk][mt][1], aH[kk][mt][2], aH[kk][mt][3], sb + o);
                    ldm_x4(aL[kk][mt][0], aL[kk][mt][1], aL[kk][mt][2], aL[kk][mt][3],
                           sb + 16384 + o);
                }
            }
            #pragma unroll
            for (int n = 0; n < 8; n++) {
                int row = wn * 64 + n * 8 + (lane & 7);
                uint32_t o = SW(row * 128 + (p * 4 + (lane >> 3)) * 16);
                uint32_t b0, b1, b2, b3, c0, c1, c2, c3;
                ldm_x4(b0, b1, b2, b3, sb + 32768 + o);
                ldm_x4(c0, c1, c2, c3, sb + 49152 + o);
                #pragma unroll
                for (int mt = 0; mt < 2; mt++) {
                    mma_f16(acc[mt][n], aH[0][mt], b0, b1);
                    mma_f16(acc[mt][n], aH[0][mt], c0, c1);
                    mma_f16(acc[mt][n], aL[0][mt], b0, b1);
                    mma_f16(acc[mt][n], aH[1][mt], b2, b3);
                    mma_f16(acc[mt][n], aH[1][mt], c2, c3);
                    mma_f16(acc[mt][n], aL[1][mt], b2, b3);
                }
            }
        }
    }

    #pragma unroll
    for (int mt = 0; mt < 2; mt++) {
        int rlo = m0 + wm * 32 + mt * 16 + gID;
        #pragma unroll
        for (int n = 0; n < 8; n++) {
            int col = n0 + wn * 64 + n * 8 + tc * 2;
            float b0 = bias[col], b1 = bias[col + 1];
            *(float2*)(out + (size_t)rlo * HID + col) =
                make_float2(acc[mt][n][0] + b0, acc[mt][n][1] + b1);
            *(float2*)(out + (size_t)(rlo + 8) * HID + col) =
                make_float2(acc[mt][n][2] + b0, acc[mt][n][3] + b1);
        }
    }
}

// ---------------------------------------------------------------------------
extern "C" void kernel_launch(void* const* d_in, const int* in_sizes, int n_in,
                              void* d_out, int out_size) {
    const float* x    = (const float*)d_in[0];
    const float* W    = (const float*)d_in[1];
    const float* bias = (const float*)d_in[2];
    float* out = (float*)d_out;

    const int ASM = 49152;
    const int PSM = 65536;
    cudaFuncSetAttribute(attn_kernel, cudaFuncAttributeMaxDynamicSharedMemorySize, ASM);
    cudaFuncSetAttribute(proj_kernel, cudaFuncAttributeMaxDynamicSharedMemorySize, PSM);

    const int nx = BATCH * SEQ * HID;
    const int nw = HID * HID;
    conv_x_kernel<<<(nx + 255) / 256, 256>>>(x, nx);
    conv_w_kernel<<<(nw + 255) / 256, 256>>>(W, nw);

    dim3 g1(SEQ / BQ, NH, BATCH);              // (16,16,2) = 512 CTAs
    attn_kernel<<<g1, 256, ASM>>>();

    dim3 g2(HID / 128, (BATCH * SEQ) / 128);   // (8,32) = 256 CTAs
    proj_kernel<<<g2, 256, PSM>>>(bias, out);
}

// round 4
// speedup vs baseline: 5.9472x; 1.2927x over previous
#include <cuda_runtime.h>
#include <cuda_fp16.h>
#include <stdint.h>

#define BATCH 2
#define SEQ   2048
#define HID   1024
#define NH    16
#define DH    64
#define BQ    64
#define BK    64
#define NT    (SEQ / BK)

// fp16 hi/lo splits in global scratch
__device__ __half g_xh[(size_t)BATCH * SEQ * HID];
__device__ __half g_xl[(size_t)BATCH * SEQ * HID];
__device__ __half g_ch[(size_t)BATCH * SEQ * HID];
__device__ __half g_cl[(size_t)BATCH * SEQ * HID];
__device__ __half g_wh[(size_t)HID * HID];
__device__ __half g_wl[(size_t)HID * HID];

// ---------------------------------------------------------------------------
__device__ __forceinline__ uint32_t smem_u32(const void* p) {
    uint32_t a;
    asm("{ .reg .u64 t; cvta.to.shared.u64 t, %1; cvt.u32.u64 %0, t; }" : "=r"(a) : "l"(p));
    return a;
}

#define SW(o) ((uint32_t)(o) ^ ((((uint32_t)(o)) >> 3) & 0x70))

__device__ __forceinline__ void ldm_x4(uint32_t& r0, uint32_t& r1, uint32_t& r2, uint32_t& r3,
                                       uint32_t addr) {
    asm volatile("ldmatrix.sync.aligned.m8n8.x4.shared.b16 {%0,%1,%2,%3}, [%4];"
                 : "=r"(r0), "=r"(r1), "=r"(r2), "=r"(r3) : "r"(addr));
}
__device__ __forceinline__ void ldm_x4t(uint32_t& r0, uint32_t& r1, uint32_t& r2, uint32_t& r3,
                                        uint32_t addr) {
    asm volatile("ldmatrix.sync.aligned.m8n8.x4.trans.shared.b16 {%0,%1,%2,%3}, [%4];"
                 : "=r"(r0), "=r"(r1), "=r"(r2), "=r"(r3) : "r"(addr));
}

__device__ __forceinline__ void mma_f16(float* c, const uint32_t* a, uint32_t b0, uint32_t b1) {
    asm volatile("mma.sync.aligned.m16n8k16.row.col.f32.f16.f16.f32 "
                 "{%0,%1,%2,%3}, {%4,%5,%6,%7}, {%8,%9}, {%0,%1,%2,%3};"
                 : "+f"(c[0]), "+f"(c[1]), "+f"(c[2]), "+f"(c[3])
                 : "r"(a[0]), "r"(a[1]), "r"(a[2]), "r"(a[3]), "r"(b0), "r"(b1));
}

__device__ __forceinline__ void cp16(uint32_t dst, const void* src) {
    asm volatile("cp.async.cg.shared.global [%0], [%1], 16;" :: "r"(dst), "l"(src));
}
#define CP_COMMIT() asm volatile("cp.async.commit_group;" ::: "memory")
#define CP_WAIT(n)  asm volatile("cp.async.wait_group %0;" :: "n"(n) : "memory")

__device__ __forceinline__ uint32_t packh(__half lo, __half hi) {
    return (uint32_t)__half_as_ushort(lo) | ((uint32_t)__half_as_ushort(hi) << 16);
}

// ---------------------------------------------------------------------------
__global__ void conv_x_kernel(const float* __restrict__ src, int n) {
    int i = blockIdx.x * blockDim.x + threadIdx.x;
    if (i < n) {
        float v = src[i];
        __half h = __float2half_rn(v);
        g_xh[i] = h;
        g_xl[i] = __float2half_rn(v - __half2float(h));
    }
}
__global__ void conv_w_kernel(const float* __restrict__ src, int n) {
    int i = blockIdx.x * blockDim.x + threadIdx.x;
    if (i < n) {
        float v = src[i];
        __half h = __float2half_rn(v);
        g_wh[i] = h;
        g_wl[i] = __float2half_rn(v - __half2float(h));
    }
}

// ---------------------------------------------------------------------------
// Flash attention: CTA = (q-tile 64, head, batch); 128 threads = 4 warps.
// smem: QH 0..8K, QL 8K..16K; K stages: s*16K+16K = {KH, KL} 8K each.
// Total 48KB. 2 CTAs/SM.
// ---------------------------------------------------------------------------
__global__ __launch_bounds__(128, 2) void attn_kernel() {
    extern __shared__ __align__(128) char sm[];
    const uint32_t sb = smem_u32(sm);
    const int tid = threadIdx.x, lane = tid & 31, wid = tid >> 5;
    const int qt = blockIdx.x, h = blockIdx.y, b = blockIdx.z;
    const int q0 = qt * BQ;
    const int gID = lane >> 2, tc = lane & 3;

    // Issue K stage-0 cp.async first (overlaps Q setup)
    {
        #pragma unroll
        for (int i = 0; i < 4; i++) {
            int e = i * 128 + tid;        // 0..511
            int row = e >> 3, ch = e & 7;
            size_t src = ((size_t)(b * SEQ + row)) * HID + h * DH + ch * 8;
            uint32_t o = SW(row * 128 + ch * 16);
            cp16(sb + 16384 + o, g_xh + src);
            cp16(sb + 24576 + o, g_xl + src);
        }
        CP_COMMIT();
    }

    // Load Q tile hi/lo (64 rows x 128B)
    #pragma unroll
    for (int i = 0; i < 4; i++) {
        int e = i * 128 + tid;            // 0..511
        int row = e >> 3, ch = e & 7;
        size_t src = ((size_t)(b * SEQ + q0 + row)) * HID + h * DH + ch * 8;
        uint32_t o = SW(row * 128 + ch * 16);
        *(uint4*)(sm + o)        = *(const uint4*)(g_xh + src);
        *(uint4*)(sm + 8192 + o) = *(const uint4*)(g_xl + src);
    }
    __syncthreads();

    // Q fragments (registers, reused across all KV tiles)
    uint32_t aQh[4][4], aQl[4][4];
    {
        int row = wid * 16 + (lane & 15);
        int chb = lane >> 4;
        #pragma unroll
        for (int ks = 0; ks < 4; ks++) {
            uint32_t o = SW(row * 128 + (ks * 2 + chb) * 16);
            ldm_x4(aQh[ks][0], aQh[ks][1], aQh[ks][2], aQh[ks][3], sb + o);
            ldm_x4(aQl[ks][0], aQl[ks][1], aQl[ks][2], aQl[ks][3], sb + 8192 + o);
        }
    }

    float o_[8][4];
    #pragma unroll
    for (int n = 0; n < 8; n++)
        #pragma unroll
        for (int j = 0; j < 4; j++) o_[n][j] = 0.0f;
    float m_lo = -1e30f, m_hi = -1e30f, l_lo = 0.0f, l_hi = 0.0f;

    for (int kt = 0; kt < NT; kt++) {
        const uint32_t kb = 16384 + (uint32_t)(kt & 1) * 16384;  // stage base
        __syncthreads();   // everyone done reading the other stage
        if (kt + 1 < NT) {
            const uint32_t nb = 16384 + (uint32_t)((kt + 1) & 1) * 16384;
            #pragma unroll
            for (int i = 0; i < 4; i++) {
                int e = i * 128 + tid;
                int row = e >> 3, ch = e & 7;
                size_t src = ((size_t)(b * SEQ + (kt + 1) * BK + row)) * HID + h * DH + ch * 8;
                uint32_t o = SW(row * 128 + ch * 16);
                cp16(nb + sb + o, g_xh + src);
                cp16(nb + sb + 8192 + o, g_xl + src);
            }
            CP_COMMIT();
            CP_WAIT(1);
        } else {
            CP_WAIT(0);
        }
        __syncthreads();   // stage kb data visible

        // ---- S = Q K^T (3-product fp16 emulation) ----
        float s[8][4];
        #pragma unroll
        for (int n = 0; n < 8; n++)
            #pragma unroll
            for (int j = 0; j < 4; j++) s[n][j] = 0.0f;

        #pragma unroll
        for (int n = 0; n < 8; n++) {
            int row = n * 8 + (lane & 7);
            #pragma unroll
            for (int p = 0; p < 2; p++) {
                uint32_t o = SW(row * 128 + (p * 4 + (lane >> 3)) * 16);
                uint32_t b0, b1, b2, b3, c0, c1, c2, c3;
                ldm_x4(b0, b1, b2, b3, sb + kb + o);
                ldm_x4(c0, c1, c2, c3, sb + kb + 8192 + o);
                mma_f16(s[n], aQh[2 * p],     b0, b1);
                mma_f16(s[n], aQh[2 * p],     c0, c1);
                mma_f16(s[n], aQl[2 * p],     b0, b1);
                mma_f16(s[n], aQh[2 * p + 1], b2, b3);
                mma_f16(s[n], aQh[2 * p + 1], c2, c3);
                mma_f16(s[n], aQl[2 * p + 1], b2, b3);
            }
        }

        // ---- online softmax ----
        const float sc = 0.125f;
        float mlo = -1e30f, mhi = -1e30f;
        #pragma unroll
        for (int n = 0; n < 8; n++) {
            mlo = fmaxf(mlo, fmaxf(s[n][0], s[n][1]));
            mhi = fmaxf(mhi, fmaxf(s[n][2], s[n][3]));
        }
        mlo = fmaxf(mlo, __shfl_xor_sync(0xffffffffu, mlo, 1));
        mlo = fmaxf(mlo, __shfl_xor_sync(0xffffffffu, mlo, 2));
        mhi = fmaxf(mhi, __shfl_xor_sync(0xffffffffu, mhi, 1));
        mhi = fmaxf(mhi, __shfl_xor_sync(0xffffffffu, mhi, 2));
        float nml = fmaxf(m_lo, mlo * sc), nmh = fmaxf(m_hi, mhi * sc);
        float clo = __expf(m_lo - nml), chi = __expf(m_hi - nmh);
        m_lo = nml; m_hi = nmh;

        float slo = 0.0f, shi = 0.0f;
        uint32_t aPh[4][4], aPl[4][4];
        #pragma unroll
        for (int n = 0; n < 8; n++) {
            float p0 = __expf(s[n][0] * sc - nml);
            float p1 = __expf(s[n][1] * sc - nml);
            float p2 = __expf(s[n][2] * sc - nmh);
            float p3 = __expf(s[n][3] * sc - nmh);
            slo += p0 + p1;
            shi += p2 + p3;
            __half h0 = __float2half_rn(p0), h1 = __float2half_rn(p1);
            __half h2 = __float2half_rn(p2), h3 = __float2half_rn(p3);
            int t = n >> 1, idx = (n & 1) * 2;
            aPh[t][idx]     = packh(h0, h1);
            aPh[t][idx + 1] = packh(h2, h3);
            aPl[t][idx]     = packh(__float2half_rn(p0 - __half2float(h0)),
                                    __float2half_rn(p1 - __half2float(h1)));
            aPl[t][idx + 1] = packh(__float2half_rn(p2 - __half2float(h2)),
                                    __float2half_rn(p3 - __half2float(h3)));
        }
        slo += __shfl_xor_sync(0xffffffffu, slo, 1);
        slo += __shfl_xor_sync(0xffffffffu, slo, 2);
        shi += __shfl_xor_sync(0xffffffffu, shi, 1);
        shi += __shfl_xor_sync(0xffffffffu, shi, 2);
        l_lo = l_lo * clo + slo;
        l_hi = l_hi * chi + shi;
        #pragma unroll
        for (int n = 0; n < 8; n++) {
            o_[n][0] *= clo; o_[n][1] *= clo;
            o_[n][2] *= chi; o_[n][3] *= chi;
        }

        // ---- O += P V (V = K tile; B frags via ldmatrix.x4.trans) ----
        #pragma unroll
        for (int n = 0; n < 8; n++) {
            #pragma unroll
            for (int p = 0; p < 2; p++) {
                int row = p * 32 + (lane >> 3) * 8 + (lane & 7);
                uint32_t o = SW(row * 128 + n * 16);
                uint32_t v0, v1, v2, v3, w0, w1, w2, w3;
                ldm_x4t(v0, v1, v2, v3, sb + kb + o);
                ldm_x4t(w0, w1, w2, w3, sb + kb + 8192 + o);
                mma_f16(o_[n], aPh[2 * p],     v0, v1);
                mma_f16(o_[n], aPh[2 * p],     w0, w1);
                mma_f16(o_[n], aPl[2 * p],     v0, v1);
                mma_f16(o_[n], aPh[2 * p + 1], v2, v3);
                mma_f16(o_[n], aPh[2 * p + 1], w2, w3);
                mma_f16(o_[n], aPl[2 * p + 1], v2, v3);
            }
        }
    }

    // ---- normalize, split to fp16 hi/lo, write ctx ----
    {
        float il = 1.0f / l_lo, ih = 1.0f / l_hi;
        size_t rlo = (size_t)(b * SEQ + q0 + wid * 16 + gID);
        size_t rhi = rlo + 8;
        #pragma unroll
        for (int n = 0; n < 8; n++) {
            int col = h * DH + n * 8 + tc * 2;
            float v0 = o_[n][0] * il, v1 = o_[n][1] * il;
            float v2 = o_[n][2] * ih, v3 = o_[n][3] * ih;
            __half h0 = __float2half_rn(v0), h1 = __float2half_rn(v1);
            __half h2 = __float2half_rn(v2), h3 = __float2half_rn(v3);
            *(uint32_t*)(g_ch + rlo * HID + col) = packh(h0, h1);
            *(uint32_t*)(g_cl + rlo * HID + col) =
                packh(__float2half_rn(v0 - __half2float(h0)),
                      __float2half_rn(v1 - __half2float(h1)));
            *(uint32_t*)(g_ch + rhi * HID + col) = packh(h2, h3);
            *(uint32_t*)(g_cl + rhi * HID + col) =
                packh(__float2half_rn(v2 - __half2float(h2)),
                      __float2half_rn(v3 - __half2float(h3)));
        }
    }
}

// ---------------------------------------------------------------------------
// Projection: out[m][n] = sum_k ctx[m][k] * W[n][k] + bias[n]
// 128x128 tile, 256 threads (8 warps 4x2), 2-stage cp.async pipeline.
// smem per stage: AH 0, AL 16K, BH 32K, BL 48K. 2 stages = 128KB.
// ---------------------------------------------------------------------------
#define PSTG 65536

__global__ __launch_bounds__(256, 1) void proj_kernel(const float* __restrict__ bias,
                                                      float* __restrict__ out) {
    extern __shared__ __align__(128) char sm[];
    const uint32_t sb = smem_u32(sm);
    const int tid = threadIdx.x, lane = tid & 31, wid = tid >> 5;
    const int wm = wid >> 1, wn = wid & 1;
    const int n0 = blockIdx.x * 128, m0 = blockIdx.y * 128;
    const int gID = lane >> 2, tc = lane & 3;

    float acc[2][8][4];
    #pragma unroll
    for (int mt = 0; mt < 2; mt++)
        #pragma unroll
        for (int n = 0; n < 8; n++)
            #pragma unroll
            for (int j = 0; j < 4; j++) acc[mt][n][j] = 0.0f;

    // prologue: issue kc=0 into stage 0
    {
        #pragma unroll
        for (int i = 0; i < 4; i++) {
            int e = i * 256 + tid;
            int row = e >> 3, ch = e & 7;
            size_t ao = ((size_t)(m0 + row)) * HID + ch * 8;
            size_t bo = ((size_t)(n0 + row)) * HID + ch * 8;
            uint32_t o = SW(row * 128 + ch * 16);
            cp16(sb + o,         g_ch + ao);
            cp16(sb + 16384 + o, g_cl + ao);
            cp16(sb + 32768 + o, g_wh + bo);
            cp16(sb + 49152 + o, g_wl + bo);
        }
        CP_COMMIT();
    }

    for (int kc = 0; kc < HID / 64; kc++) {
        const uint32_t stg = (uint32_t)(kc & 1) * PSTG;
        __syncthreads();
        if (kc + 1 < HID / 64) {
            const uint32_t ns = (uint32_t)((kc + 1) & 1) * PSTG;
            #pragma unroll
            for (int i = 0; i < 4; i++) {
                int e = i * 256 + tid;
                int row = e >> 3, ch = e & 7;
                size_t ao = ((size_t)(m0 + row)) * HID + (kc + 1) * 64 + ch * 8;
                size_t bo = ((size_t)(n0 + row)) * HID + (kc + 1) * 64 + ch * 8;
                uint32_t o = SW(row * 128 + ch * 16);
                cp16(sb + ns + o,         g_ch + ao);
                cp16(sb + ns + 16384 + o, g_cl + ao);
                cp16(sb + ns + 32768 + o, g_wh + bo);
                cp16(sb + ns + 49152 + o, g_wl + bo);
            }
            CP_COMMIT();
            CP_WAIT(1);
        } else {
            CP_WAIT(0);
        }
        __syncthreads();

        #pragma unroll
        for (int p = 0; p < 2; p++) {
            uint32_t aH[2][2][4], aL[2][2][4];
            #pragma unroll
            for (int kk = 0; kk < 2; kk++) {
                int ks = 2 * p + kk;
                #pragma unroll
                for (int mt = 0; mt < 2; mt++) {
                    int row = wm * 32 + mt * 16 + (lane & 15);
                    uint32_t o = SW(row * 128 + (ks * 2 + (lane >> 4)) * 16);
                    ldm_x4(aH[kk][mt][0], aH[kk][mt][1], aH[kk][mt][2], aH[kk][mt][3],
                           sb + stg + o);
                    ldm_x4(aL[kk][mt][0], aL[kk][mt][1], aL[kk][mt][2], aL[kk][mt][3],
                           sb + stg + 16384 + o);
                }
            }
            #pragma unroll
            for (int n = 0; n < 8; n++) {
                int row = wn * 64 + n * 8 + (lane & 7);
                uint32_t o = SW(row * 128 + (p * 4 + (lane >> 3)) * 16);
                uint32_t b0, b1, b2, b3, c0, c1, c2, c3;
                ldm_x4(b0, b1, b2, b3, sb + stg + 32768 + o);
                ldm_x4(c0, c1, c2, c3, sb + stg + 49152 + o);
                #pragma unroll
                for (int mt = 0; mt < 2; mt++) {
                    mma_f16(acc[mt][n], aH[0][mt], b0, b1);
                    mma_f16(acc[mt][n], aH[0][mt], c0, c1);
                    mma_f16(acc[mt][n], aL[0][mt], b0, b1);
                    mma_f16(acc[mt][n], aH[1][mt], b2, b3);
                    mma_f16(acc[mt][n], aH[1][mt], c2, c3);
                    mma_f16(acc[mt][n], aL[1][mt], b2, b3);
                }
            }
        }
    }

    #pragma unroll
    for (int mt = 0; mt < 2; mt++) {
        int rlo = m0 + wm * 32 + mt * 16 + gID;
        #pragma unroll
        for (int n = 0; n < 8; n++) {
            int col = n0 + wn * 64 + n * 8 + tc * 2;
            float b0 = bias[col], b1 = bias[col + 1];
            *(float2*)(out + (size_t)rlo * HID + col) =
                make_float2(acc[mt][n][0] + b0, acc[mt][n][1] + b1);
            *(float2*)(out + (size_t)(rlo + 8) * HID + col) =
                make_float2(acc[mt][n][2] + b0, acc[mt][n][3] + b1);
        }
    }
}

// ---------------------------------------------------------------------------
extern "C" void kernel_launch(void* const* d_in, const int* in_sizes, int n_in,
                              void* d_out, int out_size) {
    const float* x    = (const float*)d_in[0];
    const float* W    = (const float*)d_in[1];
    const float* bias = (const float*)d_in[2];
    float* out = (float*)d_out;

    const int ASM = 49152;          // 16KB Q + 2x16KB K stages
    const int PSM = 2 * PSTG;       // 128KB
    cudaFuncSetAttribute(attn_kernel, cudaFuncAttributeMaxDynamicSharedMemorySize, ASM);
    cudaFuncSetAttribute(proj_kernel, cudaFuncAttributeMaxDynamicSharedMemorySize, PSM);

    const int nx = BATCH * SEQ * HID;
    const int nw = HID * HID;
    conv_x_kernel<<<(nx + 255) / 256, 256>>>(x, nx);
    conv_w_kernel<<<(nw + 255) / 256, 256>>>(W, nw);

    dim3 g1(SEQ / BQ, NH, BATCH);              // (32,16,2) = 1024 CTAs
    attn_kernel<<<g1, 128, ASM>>>();

    dim3 g2(HID / 128, (BATCH * SEQ) / 128);   // (8,32) = 256 CTAs
    proj_kernel<<<g2, 256, PSM>>>(bias, out);
}

// round 5
// speedup vs baseline: 7.6691x; 1.2895x over previous
#include <cuda_runtime.h>
#include <cuda_fp16.h>
#include <stdint.h>

#define BATCH 2
#define SEQ   2048
#define HID   1024
#define NH    16
#define DH    64
#define BQ    64
#define BK    64
#define NT    (SEQ / BK)

// fp16 hi/lo splits in global scratch
__device__ __half g_xh[(size_t)BATCH * SEQ * HID];
__device__ __half g_xl[(size_t)BATCH * SEQ * HID];
__device__ __half g_ch[(size_t)BATCH * SEQ * HID];
__device__ __half g_cl[(size_t)BATCH * SEQ * HID];
__device__ __half g_wh[(size_t)HID * HID];
__device__ __half g_wl[(size_t)HID * HID];

// ---------------------------------------------------------------------------
__device__ __forceinline__ uint32_t smem_u32(const void* p) {
    uint32_t a;
    asm("{ .reg .u64 t; cvta.to.shared.u64 t, %1; cvt.u32.u64 %0, t; }" : "=r"(a) : "l"(p));
    return a;
}

#define SW(o) ((uint32_t)(o) ^ ((((uint32_t)(o)) >> 3) & 0x70))

__device__ __forceinline__ void ldm_x4(uint32_t& r0, uint32_t& r1, uint32_t& r2, uint32_t& r3,
                                       uint32_t addr) {
    asm volatile("ldmatrix.sync.aligned.m8n8.x4.shared.b16 {%0,%1,%2,%3}, [%4];"
                 : "=r"(r0), "=r"(r1), "=r"(r2), "=r"(r3) : "r"(addr));
}
__device__ __forceinline__ void ldm_x4t(uint32_t& r0, uint32_t& r1, uint32_t& r2, uint32_t& r3,
                                        uint32_t addr) {
    asm volatile("ldmatrix.sync.aligned.m8n8.x4.trans.shared.b16 {%0,%1,%2,%3}, [%4];"
                 : "=r"(r0), "=r"(r1), "=r"(r2), "=r"(r3) : "r"(addr));
}

__device__ __forceinline__ void mma_f16(float* c, const uint32_t* a, uint32_t b0, uint32_t b1) {
    asm volatile("mma.sync.aligned.m16n8k16.row.col.f32.f16.f16.f32 "
                 "{%0,%1,%2,%3}, {%4,%5,%6,%7}, {%8,%9}, {%0,%1,%2,%3};"
                 : "+f"(c[0]), "+f"(c[1]), "+f"(c[2]), "+f"(c[3])
                 : "r"(a[0]), "r"(a[1]), "r"(a[2]), "r"(a[3]), "r"(b0), "r"(b1));
}

__device__ __forceinline__ void cp16(uint32_t dst, const void* src) {
    asm volatile("cp.async.cg.shared.global [%0], [%1], 16;" :: "r"(dst), "l"(src));
}
#define CP_COMMIT() asm volatile("cp.async.commit_group;" ::: "memory")
#define CP_WAIT(n)  asm volatile("cp.async.wait_group %0;" :: "n"(n) : "memory")

__device__ __forceinline__ uint32_t packh(__half lo, __half hi) {
    return (uint32_t)__half_as_ushort(lo) | ((uint32_t)__half_as_ushort(hi) << 16);
}

// ---------------------------------------------------------------------------
// Vectorized converts: fp32 -> fp16 hi + fp16 lo residual (4 elems/thread)
// ---------------------------------------------------------------------------
__global__ void conv_x_kernel(const float* __restrict__ src, int n4) {
    int i = blockIdx.x * blockDim.x + threadIdx.x;
    if (i < n4) {
        float4 v = ((const float4*)src)[i];
        __half h0 = __float2half_rn(v.x), h1 = __float2half_rn(v.y);
        __half h2 = __float2half_rn(v.z), h3 = __float2half_rn(v.w);
        uint2 ho = make_uint2(packh(h0, h1), packh(h2, h3));
        uint2 lo = make_uint2(
            packh(__float2half_rn(v.x - __half2float(h0)), __float2half_rn(v.y - __half2float(h1))),
            packh(__float2half_rn(v.z - __half2float(h2)), __float2half_rn(v.w - __half2float(h3))));
        ((uint2*)g_xh)[i] = ho;
        ((uint2*)g_xl)[i] = lo;
    }
}
__global__ void conv_w_kernel(const float* __restrict__ src, int n4) {
    int i = blockIdx.x * blockDim.x + threadIdx.x;
    if (i < n4) {
        float4 v = ((const float4*)src)[i];
        __half h0 = __float2half_rn(v.x), h1 = __float2half_rn(v.y);
        __half h2 = __float2half_rn(v.z), h3 = __float2half_rn(v.w);
        uint2 ho = make_uint2(packh(h0, h1), packh(h2, h3));
        uint2 lo = make_uint2(
            packh(__float2half_rn(v.x - __half2float(h0)), __float2half_rn(v.y - __half2float(h1))),
            packh(__float2half_rn(v.z - __half2float(h2)), __float2half_rn(v.w - __half2float(h3))));
        ((uint2*)g_wh)[i] = ho;
        ((uint2*)g_wl)[i] = lo;
    }
}

// ---------------------------------------------------------------------------
// Flash attention: CTA = (q-tile 64, head, batch); 128 threads = 4 warps.
// smem: QH 0..8K, QL 8K..16K; K stages: 16K + s*16K = {KH, KL} 8K each. 48KB.
// S = Qh*Kh + Ql*Kh (2-product; Kl frags never loaded in S phase).
// O += Ph*Vh + Ph*Vl (2-product; no P residual).
// ---------------------------------------------------------------------------
__global__ __launch_bounds__(128, 2) void attn_kernel() {
    extern __shared__ __align__(128) char sm[];
    const uint32_t sb = smem_u32(sm);
    const int tid = threadIdx.x, lane = tid & 31, wid = tid >> 5;
    const int qt = blockIdx.x, h = blockIdx.y, b = blockIdx.z;
    const int q0 = qt * BQ;
    const int gID = lane >> 2, tc = lane & 3;

    // Issue K stage-0 cp.async first (overlaps Q setup)
    {
        #pragma unroll
        for (int i = 0; i < 4; i++) {
            int e = i * 128 + tid;        // 0..511
            int row = e >> 3, ch = e & 7;
            size_t src = ((size_t)(b * SEQ + row)) * HID + h * DH + ch * 8;
            uint32_t o = SW(row * 128 + ch * 16);
            cp16(sb + 16384 + o, g_xh + src);
            cp16(sb + 24576 + o, g_xl + src);
        }
        CP_COMMIT();
    }

    // Load Q tile hi/lo (64 rows x 128B)
    #pragma unroll
    for (int i = 0; i < 4; i++) {
        int e = i * 128 + tid;            // 0..511
        int row = e >> 3, ch = e & 7;
        size_t src = ((size_t)(b * SEQ + q0 + row)) * HID + h * DH + ch * 8;
        uint32_t o = SW(row * 128 + ch * 16);
        *(uint4*)(sm + o)        = *(const uint4*)(g_xh + src);
        *(uint4*)(sm + 8192 + o) = *(const uint4*)(g_xl + src);
    }
    __syncthreads();

    // Q fragments (registers, reused across all KV tiles)
    uint32_t aQh[4][4], aQl[4][4];
    {
        int row = wid * 16 + (lane & 15);
        int chb = lane >> 4;
        #pragma unroll
        for (int ks = 0; ks < 4; ks++) {
            uint32_t o = SW(row * 128 + (ks * 2 + chb) * 16);
            ldm_x4(aQh[ks][0], aQh[ks][1], aQh[ks][2], aQh[ks][3], sb + o);
            ldm_x4(aQl[ks][0], aQl[ks][1], aQl[ks][2], aQl[ks][3], sb + 8192 + o);
        }
    }

    float o_[8][4];
    #pragma unroll
    for (int n = 0; n < 8; n++)
        #pragma unroll
        for (int j = 0; j < 4; j++) o_[n][j] = 0.0f;
    float m_lo = -1e30f, m_hi = -1e30f, l_lo = 0.0f, l_hi = 0.0f;

    for (int kt = 0; kt < NT; kt++) {
        const uint32_t kb = 16384 + (uint32_t)(kt & 1) * 16384;  // stage base
        __syncthreads();   // everyone done reading the other stage
        if (kt + 1 < NT) {
            const uint32_t nb = 16384 + (uint32_t)((kt + 1) & 1) * 16384;
            #pragma unroll
            for (int i = 0; i < 4; i++) {
                int e = i * 128 + tid;
                int row = e >> 3, ch = e & 7;
                size_t src = ((size_t)(b * SEQ + (kt + 1) * BK + row)) * HID + h * DH + ch * 8;
                uint32_t o = SW(row * 128 + ch * 16);
                cp16(nb + sb + o, g_xh + src);
                cp16(nb + sb + 8192 + o, g_xl + src);
            }
            CP_COMMIT();
            CP_WAIT(1);
        } else {
            CP_WAIT(0);
        }
        __syncthreads();   // stage kb data visible

        // ---- S = (Qh + Ql) K_h^T  (Kh frags reused for both products) ----
        float s[8][4];
        #pragma unroll
        for (int n = 0; n < 8; n++)
            #pragma unroll
            for (int j = 0; j < 4; j++) s[n][j] = 0.0f;

        #pragma unroll
        for (int n = 0; n < 8; n++) {
            int row = n * 8 + (lane & 7);
            #pragma unroll
            for (int p = 0; p < 2; p++) {
                uint32_t o = SW(row * 128 + (p * 4 + (lane >> 3)) * 16);
                uint32_t b0, b1, b2, b3;
                ldm_x4(b0, b1, b2, b3, sb + kb + o);
                mma_f16(s[n], aQh[2 * p],     b0, b1);
                mma_f16(s[n], aQl[2 * p],     b0, b1);
                mma_f16(s[n], aQh[2 * p + 1], b2, b3);
                mma_f16(s[n], aQl[2 * p + 1], b2, b3);
            }
        }

        // ---- online softmax ----
        const float sc = 0.125f;
        float mlo = -1e30f, mhi = -1e30f;
        #pragma unroll
        for (int n = 0; n < 8; n++) {
            mlo = fmaxf(mlo, fmaxf(s[n][0], s[n][1]));
            mhi = fmaxf(mhi, fmaxf(s[n][2], s[n][3]));
        }
        mlo = fmaxf(mlo, __shfl_xor_sync(0xffffffffu, mlo, 1));
        mlo = fmaxf(mlo, __shfl_xor_sync(0xffffffffu, mlo, 2));
        mhi = fmaxf(mhi, __shfl_xor_sync(0xffffffffu, mhi, 1));
        mhi = fmaxf(mhi, __shfl_xor_sync(0xffffffffu, mhi, 2));
        float nml = fmaxf(m_lo, mlo * sc), nmh = fmaxf(m_hi, mhi * sc);
        float clo = __expf(m_lo - nml), chi = __expf(m_hi - nmh);
        m_lo = nml; m_hi = nmh;

        float slo = 0.0f, shi = 0.0f;
        uint32_t aPh[4][4];
        #pragma unroll
        for (int n = 0; n < 8; n++) {
            float p0 = __expf(s[n][0] * sc - nml);
            float p1 = __expf(s[n][1] * sc - nml);
            float p2 = __expf(s[n][2] * sc - nmh);
            float p3 = __expf(s[n][3] * sc - nmh);
            slo += p0 + p1;
            shi += p2 + p3;
            int t = n >> 1, idx = (n & 1) * 2;
            aPh[t][idx]     = packh(__float2half_rn(p0), __float2half_rn(p1));
            aPh[t][idx + 1] = packh(__float2half_rn(p2), __float2half_rn(p3));
        }
        slo += __shfl_xor_sync(0xffffffffu, slo, 1);
        slo += __shfl_xor_sync(0xffffffffu, slo, 2);
        shi += __shfl_xor_sync(0xffffffffu, shi, 1);
        shi += __shfl_xor_sync(0xffffffffu, shi, 2);
        l_lo = l_lo * clo + slo;
        l_hi = l_hi * chi + shi;
        #pragma unroll
        for (int n = 0; n < 8; n++) {
            o_[n][0] *= clo; o_[n][1] *= clo;
            o_[n][2] *= chi; o_[n][3] *= chi;
        }

        // ---- O += Ph (Vh + Vl)  (V = K tile; trans ldmatrix) ----
        #pragma unroll
        for (int n = 0; n < 8; n++) {
            #pragma unroll
            for (int p = 0; p < 2; p++) {
                int row = p * 32 + (lane >> 3) * 8 + (lane & 7);
                uint32_t o = SW(row * 128 + n * 16);
                uint32_t v0, v1, v2, v3, w0, w1, w2, w3;
                ldm_x4t(v0, v1, v2, v3, sb + kb + o);
                ldm_x4t(w0, w1, w2, w3, sb + kb + 8192 + o);
                mma_f16(o_[n], aPh[2 * p],     v0, v1);
                mma_f16(o_[n], aPh[2 * p],     w0, w1);
                mma_f16(o_[n], aPh[2 * p + 1], v2, v3);
                mma_f16(o_[n], aPh[2 * p + 1], w2, w3);
            }
        }
    }

    // ---- normalize, split to fp16 hi/lo, write ctx ----
    {
        float il = 1.0f / l_lo, ih = 1.0f / l_hi;
        size_t rlo = (size_t)(b * SEQ + q0 + wid * 16 + gID);
        size_t rhi = rlo + 8;
        #pragma unroll
        for (int n = 0; n < 8; n++) {
            int col = h * DH + n * 8 + tc * 2;
            float v0 = o_[n][0] * il, v1 = o_[n][1] * il;
            float v2 = o_[n][2] * ih, v3 = o_[n][3] * ih;
            __half h0 = __float2half_rn(v0), h1 = __float2half_rn(v1);
            __half h2 = __float2half_rn(v2), h3 = __float2half_rn(v3);
            *(uint32_t*)(g_ch + rlo * HID + col) = packh(h0, h1);
            *(uint32_t*)(g_cl + rlo * HID + col) =
                packh(__float2half_rn(v0 - __half2float(h0)),
                      __float2half_rn(v1 - __half2float(h1)));
            *(uint32_t*)(g_ch + rhi * HID + col) = packh(h2, h3);
            *(uint32_t*)(g_cl + rhi * HID + col) =
                packh(__float2half_rn(v2 - __half2float(h2)),
                      __float2half_rn(v3 - __half2float(h3)));
        }
    }
}

// ---------------------------------------------------------------------------
// Projection: out[m][n] = sum_k ctx[m][k] * W[n][k] + bias[n]
// 128x128 tile, 256 threads (8 warps 4x2), 2-stage cp.async pipeline.
// smem per stage: AH 0, AL 16K, BH 32K, BL 48K. 2 stages = 128KB.
// ---------------------------------------------------------------------------
#define PSTG 65536

__global__ __launch_bounds__(256, 1) void proj_kernel(const float* __restrict__ bias,
                                                      float* __restrict__ out) {
    extern __shared__ __align__(128) char sm[];
    const uint32_t sb = smem_u32(sm);
    const int tid = threadIdx.x, lane = tid & 31, wid = tid >> 5;
    const int wm = wid >> 1, wn = wid & 1;
    const int n0 = blockIdx.x * 128, m0 = blockIdx.y * 128;
    const int gID = lane >> 2, tc = lane & 3;

    float acc[2][8][4];
    #pragma unroll
    for (int mt = 0; mt < 2; mt++)
        #pragma unroll
        for (int n = 0; n < 8; n++)
            #pragma unroll
            for (int j = 0; j < 4; j++) acc[mt][n][j] = 0.0f;

    // prologue: issue kc=0 into stage 0
    {
        #pragma unroll
        for (int i = 0; i < 4; i++) {
            int e = i * 256 + tid;
            int row = e >> 3, ch = e & 7;
            size_t ao = ((size_t)(m0 + row)) * HID + ch * 8;
            size_t bo = ((size_t)(n0 + row)) * HID + ch * 8;
            uint32_t o = SW(row * 128 + ch * 16);
            cp16(sb + o,         g_ch + ao);
            cp16(sb + 16384 + o, g_cl + ao);
            cp16(sb + 32768 + o, g_wh + bo);
            cp16(sb + 49152 + o, g_wl + bo);
        }
        CP_COMMIT();
    }

    for (int kc = 0; kc < HID / 64; kc++) {
        const uint32_t stg = (uint32_t)(kc & 1) * PSTG;
        __syncthreads();
        if (kc + 1 < HID / 64) {
            const uint32_t ns = (uint32_t)((kc + 1) & 1) * PSTG;
            #pragma unroll
            for (int i = 0; i < 4; i++) {
                int e = i * 256 + tid;
                int row = e >> 3, ch = e & 7;
                size_t ao = ((size_t)(m0 + row)) * HID + (kc + 1) * 64 + ch * 8;
                size_t bo = ((size_t)(n0 + row)) * HID + (kc + 1) * 64 + ch * 8;
                uint32_t o = SW(row * 128 + ch * 16);
                cp16(sb + ns + o,         g_ch + ao);
                cp16(sb + ns + 16384 + o, g_cl + ao);
                cp16(sb + ns + 32768 + o, g_wh + bo);
                cp16(sb + ns + 49152 + o, g_wl + bo);
            }
            CP_COMMIT();
            CP_WAIT(1);
        } else {
            CP_WAIT(0);
        }
        __syncthreads();

        #pragma unroll
        for (int p = 0; p < 2; p++) {
            uint32_t aH[2][2][4], aL[2][2][4];
            #pragma unroll
            for (int kk = 0; kk < 2; kk++) {
                int ks = 2 * p + kk;
                #pragma unroll
                for (int mt = 0; mt < 2; mt++) {
                    int row = wm * 32 + mt * 16 + (lane & 15);
                    uint32_t o = SW(row * 128 + (ks * 2 + (lane >> 4)) * 16);
                    ldm_x4(aH[kk][mt][0], aH[kk][mt][1], aH[kk][mt][2], aH[kk][mt][3],
                           sb + stg + o);
                    ldm_x4(aL[kk][mt][0], aL[kk][mt][1], aL[kk][mt][2], aL[kk][mt][3],
                           sb + stg + 16384 + o);
                }
            }
            #pragma unroll
            for (int n = 0; n < 8; n++) {
                int row = wn * 64 + n * 8 + (lane & 7);
                uint32_t o = SW(row * 128 + (p * 4 + (lane >> 3)) * 16);
                uint32_t b0, b1, b2, b3, c0, c1, c2, c3;
                ldm_x4(b0, b1, b2, b3, sb + stg + 32768 + o);
                ldm_x4(c0, c1, c2, c3, sb + stg + 49152 + o);
                #pragma unroll
                for (int mt = 0; mt < 2; mt++) {
                    mma_f16(acc[mt][n], aH[0][mt], b0, b1);
                    mma_f16(acc[mt][n], aH[0][mt], c0, c1);
                    mma_f16(acc[mt][n], aL[0][mt], b0, b1);
                    mma_f16(acc[mt][n], aH[1][mt], b2, b3);
                    mma_f16(acc[mt][n], aH[1][mt], c2, c3);
                    mma_f16(acc[mt][n], aL[1][mt], b2, b3);
                }
            }
        }
    }

    #pragma unroll
    for (int mt = 0; mt < 2; mt++) {
        int rlo = m0 + wm * 32 + mt * 16 + gID;
        #pragma unroll
        for (int n = 0; n < 8; n++) {
            int col = n0 + wn * 64 + n * 8 + tc * 2;
            float b0 = bias[col], b1 = bias[col + 1];
            *(float2*)(out + (size_t)rlo * HID + col) =
                make_float2(acc[mt][n][0] + b0, acc[mt][n][1] + b1);
            *(float2*)(out + (size_t)(rlo + 8) * HID + col) =
                make_float2(acc[mt][n][2] + b0, acc[mt][n][3] + b1);
        }
    }
}

// ---------------------------------------------------------------------------
extern "C" void kernel_launch(void* const* d_in, const int* in_sizes, int n_in,
                              void* d_out, int out_size) {
    const float* x    = (const float*)d_in[0];
    const float* W    = (const float*)d_in[1];
    const float* bias = (const float*)d_in[2];
    float* out = (float*)d_out;

    const int ASM = 49152;          // 16KB Q + 2x16KB K stages
    const int PSM = 2 * PSTG;       // 128KB
    cudaFuncSetAttribute(attn_kernel, cudaFuncAttributeMaxDynamicSharedMemorySize, ASM);
    cudaFuncSetAttribute(proj_kernel, cudaFuncAttributeMaxDynamicSharedMemorySize, PSM);

    const int nx4 = (BATCH * SEQ * HID) / 4;
    const int nw4 = (HID * HID) / 4;
    conv_x_kernel<<<(nx4 + 255) / 256, 256>>>(x, nx4);
    conv_w_kernel<<<(nw4 + 255) / 256, 256>>>(W, nw4);

    dim3 g1(SEQ / BQ, NH, BATCH);              // (32,16,2) = 1024 CTAs
    attn_kernel<<<g1, 128, ASM>>>();

    dim3 g2(HID / 128, (BATCH * SEQ) / 128);   // (8,32) = 256 CTAs
    proj_kernel<<<g2, 256, PSM>>>(bias, out);
}

// round 6
// speedup vs baseline: 8.7553x; 1.1416x over previous
#include <cuda_runtime.h>
#include <cuda_fp16.h>
#include <stdint.h>

#define BATCH 2
#define SEQ   2048
#define HID   1024
#define NH    16
#define DH    64
#define BQ    64
#define BK    64
#define NT    (SEQ / BK)

// fp16 hi/lo splits in global scratch
__device__ __half g_xh[(size_t)BATCH * SEQ * HID];
__device__ __half g_xl[(size_t)BATCH * SEQ * HID];
__device__ __half g_ch[(size_t)BATCH * SEQ * HID];
__device__ __half g_wh[(size_t)HID * HID];
__device__ __half g_wl[(size_t)HID * HID];

// ---------------------------------------------------------------------------
__device__ __forceinline__ uint32_t smem_u32(const void* p) {
    uint32_t a;
    asm("{ .reg .u64 t; cvta.to.shared.u64 t, %1; cvt.u32.u64 %0, t; }" : "=r"(a) : "l"(p));
    return a;
}

#define SW(o) ((uint32_t)(o) ^ ((((uint32_t)(o)) >> 3) & 0x70))

__device__ __forceinline__ void ldm_x4(uint32_t& r0, uint32_t& r1, uint32_t& r2, uint32_t& r3,
                                       uint32_t addr) {
    asm volatile("ldmatrix.sync.aligned.m8n8.x4.shared.b16 {%0,%1,%2,%3}, [%4];"
                 : "=r"(r0), "=r"(r1), "=r"(r2), "=r"(r3) : "r"(addr));
}
__device__ __forceinline__ void ldm_x4t(uint32_t& r0, uint32_t& r1, uint32_t& r2, uint32_t& r3,
                                        uint32_t addr) {
    asm volatile("ldmatrix.sync.aligned.m8n8.x4.trans.shared.b16 {%0,%1,%2,%3}, [%4];"
                 : "=r"(r0), "=r"(r1), "=r"(r2), "=r"(r3) : "r"(addr));
}

__device__ __forceinline__ void mma_f16(float* c, const uint32_t* a, uint32_t b0, uint32_t b1) {
    asm volatile("mma.sync.aligned.m16n8k16.row.col.f32.f16.f16.f32 "
                 "{%0,%1,%2,%3}, {%4,%5,%6,%7}, {%8,%9}, {%0,%1,%2,%3};"
                 : "+f"(c[0]), "+f"(c[1]), "+f"(c[2]), "+f"(c[3])
                 : "r"(a[0]), "r"(a[1]), "r"(a[2]), "r"(a[3]), "r"(b0), "r"(b1));
}

__device__ __forceinline__ void cp16(uint32_t dst, const void* src) {
    asm volatile("cp.async.cg.shared.global [%0], [%1], 16;" :: "r"(dst), "l"(src));
}
#define CP_COMMIT() asm volatile("cp.async.commit_group;" ::: "memory")
#define CP_WAIT(n)  asm volatile("cp.async.wait_group %0;" :: "n"(n) : "memory")

__device__ __forceinline__ uint32_t packh(__half lo, __half hi) {
    return (uint32_t)__half_as_ushort(lo) | ((uint32_t)__half_as_ushort(hi) << 16);
}

// ---------------------------------------------------------------------------
// Vectorized converts: fp32 -> fp16 hi + fp16 lo residual (4 elems/thread)
// ---------------------------------------------------------------------------
__global__ void conv_x_kernel(const float* __restrict__ src, int n4) {
    int i = blockIdx.x * blockDim.x + threadIdx.x;
    if (i < n4) {
        float4 v = ((const float4*)src)[i];
        __half h0 = __float2half_rn(v.x), h1 = __float2half_rn(v.y);
        __half h2 = __float2half_rn(v.z), h3 = __float2half_rn(v.w);
        ((uint2*)g_xh)[i] = make_uint2(packh(h0, h1), packh(h2, h3));
        ((uint2*)g_xl)[i] = make_uint2(
            packh(__float2half_rn(v.x - __half2float(h0)), __float2half_rn(v.y - __half2float(h1))),
            packh(__float2half_rn(v.z - __half2float(h2)), __float2half_rn(v.w - __half2float(h3))));
    }
}
__global__ void conv_w_kernel(const float* __restrict__ src, int n4) {
    int i = blockIdx.x * blockDim.x + threadIdx.x;
    if (i < n4) {
        float4 v = ((const float4*)src)[i];
        __half h0 = __float2half_rn(v.x), h1 = __float2half_rn(v.y);
        __half h2 = __float2half_rn(v.z), h3 = __float2half_rn(v.w);
        ((uint2*)g_wh)[i] = make_uint2(packh(h0, h1), packh(h2, h3));
        ((uint2*)g_wl)[i] = make_uint2(
            packh(__float2half_rn(v.x - __half2float(h0)), __float2half_rn(v.y - __half2float(h1))),
            packh(__float2half_rn(v.z - __half2float(h2)), __float2half_rn(v.w - __half2float(h3))));
    }
}

// ---------------------------------------------------------------------------
// Flash attention: CTA = (q-tile 64, head, batch); 128 threads = 4 warps.
// smem: QH 0..8K, QL 8K..16K; K stages (Kh only): 16K + s*8K. Total 32KB.
// S = Qh*Kh + Ql*Kh ;  O += Ph*Vh  (V = K tile).
// ---------------------------------------------------------------------------
__global__ __launch_bounds__(128, 2) void attn_kernel() {
    extern __shared__ __align__(128) char sm[];
    const uint32_t sb = smem_u32(sm);
    const int tid = threadIdx.x, lane = tid & 31, wid = tid >> 5;
    const int qt = blockIdx.x, h = blockIdx.y, b = blockIdx.z;
    const int q0 = qt * BQ;
    const int gID = lane >> 2, tc = lane & 3;

    // Issue K stage-0 cp.async first (overlaps Q setup)
    {
        #pragma unroll
        for (int i = 0; i < 4; i++) {
            int e = i * 128 + tid;        // 0..511
            int row = e >> 3, ch = e & 7;
            size_t src = ((size_t)(b * SEQ + row)) * HID + h * DH + ch * 8;
            cp16(sb + 16384 + SW(row * 128 + ch * 16), g_xh + src);
        }
        CP_COMMIT();
    }

    // Load Q tile hi/lo (64 rows x 128B)
    #pragma unroll
    for (int i = 0; i < 4; i++) {
        int e = i * 128 + tid;            // 0..511
        int row = e >> 3, ch = e & 7;
        size_t src = ((size_t)(b * SEQ + q0 + row)) * HID + h * DH + ch * 8;
        uint32_t o = SW(row * 128 + ch * 16);
        *(uint4*)(sm + o)        = *(const uint4*)(g_xh + src);
        *(uint4*)(sm + 8192 + o) = *(const uint4*)(g_xl + src);
    }
    __syncthreads();

    // Q fragments (registers, reused across all KV tiles)
    uint32_t aQh[4][4], aQl[4][4];
    {
        int row = wid * 16 + (lane & 15);
        int chb = lane >> 4;
        #pragma unroll
        for (int ks = 0; ks < 4; ks++) {
            uint32_t o = SW(row * 128 + (ks * 2 + chb) * 16);
            ldm_x4(aQh[ks][0], aQh[ks][1], aQh[ks][2], aQh[ks][3], sb + o);
            ldm_x4(aQl[ks][0], aQl[ks][1], aQl[ks][2], aQl[ks][3], sb + 8192 + o);
        }
    }

    float o_[8][4];
    #pragma unroll
    for (int n = 0; n < 8; n++)
        #pragma unroll
        for (int j = 0; j < 4; j++) o_[n][j] = 0.0f;
    float m_lo = -1e30f, m_hi = -1e30f, l_lo = 0.0f, l_hi = 0.0f;

    for (int kt = 0; kt < NT; kt++) {
        const uint32_t kb = 16384 + (uint32_t)(kt & 1) * 8192;  // stage base
        __syncthreads();   // everyone done reading the other stage
        if (kt + 1 < NT) {
            const uint32_t nb = 16384 + (uint32_t)((kt + 1) & 1) * 8192;
            #pragma unroll
            for (int i = 0; i < 4; i++) {
                int e = i * 128 + tid;
                int row = e >> 3, ch = e & 7;
                size_t src = ((size_t)(b * SEQ + (kt + 1) * BK + row)) * HID + h * DH + ch * 8;
                cp16(nb + sb + SW(row * 128 + ch * 16), g_xh + src);
            }
            CP_COMMIT();
            CP_WAIT(1);
        } else {
            CP_WAIT(0);
        }
        __syncthreads();   // stage kb data visible

        // ---- S = (Qh + Ql) K_h^T ----
        float s[8][4];
        #pragma unroll
        for (int n = 0; n < 8; n++)
            #pragma unroll
            for (int j = 0; j < 4; j++) s[n][j] = 0.0f;

        #pragma unroll
        for (int n = 0; n < 8; n++) {
            int row = n * 8 + (lane & 7);
            #pragma unroll
            for (int p = 0; p < 2; p++) {
                uint32_t o = SW(row * 128 + (p * 4 + (lane >> 3)) * 16);
                uint32_t b0, b1, b2, b3;
                ldm_x4(b0, b1, b2, b3, sb + kb + o);
                mma_f16(s[n], aQh[2 * p],     b0, b1);
                mma_f16(s[n], aQl[2 * p],     b0, b1);
                mma_f16(s[n], aQh[2 * p + 1], b2, b3);
                mma_f16(s[n], aQl[2 * p + 1], b2, b3);
            }
        }

        // ---- online softmax ----
        const float sc = 0.125f;
        float mlo = -1e30f, mhi = -1e30f;
        #pragma unroll
        for (int n = 0; n < 8; n++) {
            mlo = fmaxf(mlo, fmaxf(s[n][0], s[n][1]));
            mhi = fmaxf(mhi, fmaxf(s[n][2], s[n][3]));
        }
        mlo = fmaxf(mlo, __shfl_xor_sync(0xffffffffu, mlo, 1));
        mlo = fmaxf(mlo, __shfl_xor_sync(0xffffffffu, mlo, 2));
        mhi = fmaxf(mhi, __shfl_xor_sync(0xffffffffu, mhi, 1));
        mhi = fmaxf(mhi, __shfl_xor_sync(0xffffffffu, mhi, 2));
        float nml = fmaxf(m_lo, mlo * sc), nmh = fmaxf(m_hi, mhi * sc);
        float clo = __expf(m_lo - nml), chi = __expf(m_hi - nmh);
        m_lo = nml; m_hi = nmh;

        float slo = 0.0f, shi = 0.0f;
        uint32_t aPh[4][4];
        #pragma unroll
        for (int n = 0; n < 8; n++) {
            float p0 = __expf(s[n][0] * sc - nml);
            float p1 = __expf(s[n][1] * sc - nml);
            float p2 = __expf(s[n][2] * sc - nmh);
            float p3 = __expf(s[n][3] * sc - nmh);
            slo += p0 + p1;
            shi += p2 + p3;
            int t = n >> 1, idx = (n & 1) * 2;
            aPh[t][idx]     = packh(__float2half_rn(p0), __float2half_rn(p1));
            aPh[t][idx + 1] = packh(__float2half_rn(p2), __float2half_rn(p3));
        }
        slo += __shfl_xor_sync(0xffffffffu, slo, 1);
        slo += __shfl_xor_sync(0xffffffffu, slo, 2);
        shi += __shfl_xor_sync(0xffffffffu, shi, 1);
        shi += __shfl_xor_sync(0xffffffffu, shi, 2);
        l_lo = l_lo * clo + slo;
        l_hi = l_hi * chi + shi;
        #pragma unroll
        for (int n = 0; n < 8; n++) {
            o_[n][0] *= clo; o_[n][1] *= clo;
            o_[n][2] *= chi; o_[n][3] *= chi;
        }

        // ---- O += Ph * Vh  (V = K tile; trans ldmatrix) ----
        #pragma unroll
        for (int n = 0; n < 8; n++) {
            #pragma unroll
            for (int p = 0; p < 2; p++) {
                int row = p * 32 + (lane >> 3) * 8 + (lane & 7);
                uint32_t o = SW(row * 128 + n * 16);
                uint32_t v0, v1, v2, v3;
                ldm_x4t(v0, v1, v2, v3, sb + kb + o);
                mma_f16(o_[n], aPh[2 * p],     v0, v1);
                mma_f16(o_[n], aPh[2 * p + 1], v2, v3);
            }
        }
    }

    // ---- normalize, write ctx (hi only; lo correction dropped in proj) ----
    {
        float il = 1.0f / l_lo, ih = 1.0f / l_hi;
        size_t rlo = (size_t)(b * SEQ + q0 + wid * 16 + gID);
        size_t rhi = rlo + 8;
        #pragma unroll
        for (int n = 0; n < 8; n++) {
            int col = h * DH + n * 8 + tc * 2;
            *(uint32_t*)(g_ch + rlo * HID + col) =
                packh(__float2half_rn(o_[n][0] * il), __float2half_rn(o_[n][1] * il));
            *(uint32_t*)(g_ch + rhi * HID + col) =
                packh(__float2half_rn(o_[n][2] * ih), __float2half_rn(o_[n][3] * ih));
        }
    }
}

// ---------------------------------------------------------------------------
// Projection: out[m][n] = sum_k ctx_h[m][k] * (W_h + W_l)[n][k] + bias[n]
// 128x128 tile, 256 threads (8 warps 4x2), 2-stage cp.async pipeline.
// smem per stage: AH 0, BH 16K, BL 32K. 2 stages = 96KB.
// ---------------------------------------------------------------------------
#define PSTG 49152

__global__ __launch_bounds__(256, 1) void proj_kernel(const float* __restrict__ bias,
                                                      float* __restrict__ out) {
    extern __shared__ __align__(128) char sm[];
    const uint32_t sb = smem_u32(sm);
    const int tid = threadIdx.x, lane = tid & 31, wid = tid >> 5;
    const int wm = wid >> 1, wn = wid & 1;
    const int n0 = blockIdx.x * 128, m0 = blockIdx.y * 128;
    const int gID = lane >> 2, tc = lane & 3;

    float acc[2][8][4];
    #pragma unroll
    for (int mt = 0; mt < 2; mt++)
        #pragma unroll
        for (int n = 0; n < 8; n++)
            #pragma unroll
            for (int j = 0; j < 4; j++) acc[mt][n][j] = 0.0f;

    // prologue: issue kc=0 into stage 0
    {
        #pragma unroll
        for (int i = 0; i < 4; i++) {
            int e = i * 256 + tid;
            int row = e >> 3, ch = e & 7;
            size_t ao = ((size_t)(m0 + row)) * HID + ch * 8;
            size_t bo = ((size_t)(n0 + row)) * HID + ch * 8;
            uint32_t o = SW(row * 128 + ch * 16);
            cp16(sb + o,         g_ch + ao);
            cp16(sb + 16384 + o, g_wh + bo);
            cp16(sb + 32768 + o, g_wl + bo);
        }
        CP_COMMIT();
    }

    for (int kc = 0; kc < HID / 64; kc++) {
        const uint32_t stg = (uint32_t)(kc & 1) * PSTG;
        __syncthreads();
        if (kc + 1 < HID / 64) {
            const uint32_t ns = (uint32_t)((kc + 1) & 1) * PSTG;
            #pragma unroll
            for (int i = 0; i < 4; i++) {
                int e = i * 256 + tid;
                int row = e >> 3, ch = e & 7;
                size_t ao = ((size_t)(m0 + row)) * HID + (kc + 1) * 64 + ch * 8;
                size_t bo = ((size_t)(n0 + row)) * HID + (kc + 1) * 64 + ch * 8;
                uint32_t o = SW(row * 128 + ch * 16);
                cp16(sb + ns + o,         g_ch + ao);
                cp16(sb + ns + 16384 + o, g_wh + bo);
                cp16(sb + ns + 32768 + o, g_wl + bo);
            }
            CP_COMMIT();
            CP_WAIT(1);
        } else {
            CP_WAIT(0);
        }
        __syncthreads();

        #pragma unroll
        for (int p = 0; p < 2; p++) {
            uint32_t aH[2][2][4];
            #pragma unroll
            for (int kk = 0; kk < 2; kk++) {
                int ks = 2 * p + kk;
                #pragma unroll
                for (int mt = 0; mt < 2; mt++) {
                    int row = wm * 32 + mt * 16 + (lane & 15);
                    uint32_t o = SW(row * 128 + (ks * 2 + (lane >> 4)) * 16);
                    ldm_x4(aH[kk][mt][0], aH[kk][mt][1], aH[kk][mt][2], aH[kk][mt][3],
                           sb + stg + o);
                }
            }
            #pragma unroll
            for (int n = 0; n < 8; n++) {
                int row = wn * 64 + n * 8 + (lane & 7);
                uint32_t o = SW(row * 128 + (p * 4 + (lane >> 3)) * 16);
                uint32_t b0, b1, b2, b3, c0, c1, c2, c3;
                ldm_x4(b0, b1, b2, b3, sb + stg + 16384 + o);
                ldm_x4(c0, c1, c2, c3, sb + stg + 32768 + o);
                #pragma unroll
                for (int mt = 0; mt < 2; mt++) {
                    mma_f16(acc[mt][n], aH[0][mt], b0, b1);
                    mma_f16(acc[mt][n], aH[0][mt], c0, c1);
                    mma_f16(acc[mt][n], aH[1][mt], b2, b3);
                    mma_f16(acc[mt][n], aH[1][mt], c2, c3);
                }
            }
        }
    }

    #pragma unroll
    for (int mt = 0; mt < 2; mt++) {
        int rlo = m0 + wm * 32 + mt * 16 + gID;
        #pragma unroll
        for (int n = 0; n < 8; n++) {
            int col = n0 + wn * 64 + n * 8 + tc * 2;
            float b0 = bias[col], b1 = bias[col + 1];
            *(float2*)(out + (size_t)rlo * HID + col) =
                make_float2(acc[mt][n][0] + b0, acc[mt][n][1] + b1);
            *(float2*)(out + (size_t)(rlo + 8) * HID + col) =
                make_float2(acc[mt][n][2] + b0, acc[mt][n][3] + b1);
        }
    }
}

// ---------------------------------------------------------------------------
extern "C" void kernel_launch(void* const* d_in, const int* in_sizes, int n_in,
                              void* d_out, int out_size) {
    const float* x    = (const float*)d_in[0];
    const float* W    = (const float*)d_in[1];
    const float* bias = (const float*)d_in[2];
    float* out = (float*)d_out;

    const int ASM = 32768;          // 16KB Q + 2x8KB K stages
    const int PSM = 2 * PSTG;       // 96KB
    cudaFuncSetAttribute(attn_kernel, cudaFuncAttributeMaxDynamicSharedMemorySize, ASM);
    cudaFuncSetAttribute(proj_kernel, cudaFuncAttributeMaxDynamicSharedMemorySize, PSM);

    const int nx4 = (BATCH * SEQ * HID) / 4;
    const int nw4 = (HID * HID) / 4;
    conv_x_kernel<<<(nx4 + 255) / 256, 256>>>(x, nx4);
    conv_w_kernel<<<(nw4 + 255) / 256, 256>>>(W, nw4);

    dim3 g1(SEQ / BQ, NH, BATCH);              // (32,16,2) = 1024 CTAs
    attn_kernel<<<g1, 128, ASM>>>();

    dim3 g2(HID / 128, (BATCH * SEQ) / 128);   // (8,32) = 256 CTAs
    proj_kernel<<<g2, 256, PSM>>>(bias, out);
}

// round 7
// speedup vs baseline: 12.6641x; 1.4465x over previous
#include <cuda_runtime.h>
#include <cuda_fp16.h>
#include <stdint.h>

#define BATCH 2
#define SEQ   2048
#define HID   1024
#define NH    16
#define DH    64
#define BQ    64
#define BK    64
#define NT    (SEQ / BK)

// fp16 casts in global scratch (single precision level, fp32 accumulate in MMA)
__device__ __half g_xh[(size_t)BATCH * SEQ * HID];
__device__ __half g_ch[(size_t)BATCH * SEQ * HID];
__device__ __half g_wh[(size_t)HID * HID];

// ---------------------------------------------------------------------------
__device__ __forceinline__ uint32_t smem_u32(const void* p) {
    uint32_t a;
    asm("{ .reg .u64 t; cvta.to.shared.u64 t, %1; cvt.u32.u64 %0, t; }" : "=r"(a) : "l"(p));
    return a;
}

#define SW(o) ((uint32_t)(o) ^ ((((uint32_t)(o)) >> 3) & 0x70))

__device__ __forceinline__ void ldm_x4(uint32_t& r0, uint32_t& r1, uint32_t& r2, uint32_t& r3,
                                       uint32_t addr) {
    asm volatile("ldmatrix.sync.aligned.m8n8.x4.shared.b16 {%0,%1,%2,%3}, [%4];"
                 : "=r"(r0), "=r"(r1), "=r"(r2), "=r"(r3) : "r"(addr));
}
__device__ __forceinline__ void ldm_x4t(uint32_t& r0, uint32_t& r1, uint32_t& r2, uint32_t& r3,
                                        uint32_t addr) {
    asm volatile("ldmatrix.sync.aligned.m8n8.x4.trans.shared.b16 {%0,%1,%2,%3}, [%4];"
                 : "=r"(r0), "=r"(r1), "=r"(r2), "=r"(r3) : "r"(addr));
}

__device__ __forceinline__ void mma_f16(float* c, const uint32_t* a, uint32_t b0, uint32_t b1) {
    asm volatile("mma.sync.aligned.m16n8k16.row.col.f32.f16.f16.f32 "
                 "{%0,%1,%2,%3}, {%4,%5,%6,%7}, {%8,%9}, {%0,%1,%2,%3};"
                 : "+f"(c[0]), "+f"(c[1]), "+f"(c[2]), "+f"(c[3])
                 : "r"(a[0]), "r"(a[1]), "r"(a[2]), "r"(a[3]), "r"(b0), "r"(b1));
}

__device__ __forceinline__ void cp16(uint32_t dst, const void* src) {
    asm volatile("cp.async.cg.shared.global [%0], [%1], 16;" :: "r"(dst), "l"(src));
}
#define CP_COMMIT() asm volatile("cp.async.commit_group;" ::: "memory")
#define CP_WAIT(n)  asm volatile("cp.async.wait_group %0;" :: "n"(n) : "memory")

__device__ __forceinline__ uint32_t packh(__half lo, __half hi) {
    return (uint32_t)__half_as_ushort(lo) | ((uint32_t)__half_as_ushort(hi) << 16);
}

// ---------------------------------------------------------------------------
// Converts: fp32 -> fp16 (4 elems/thread)
// ---------------------------------------------------------------------------
__global__ void conv_x_kernel(const float* __restrict__ src, int n4) {
    int i = blockIdx.x * blockDim.x + threadIdx.x;
    if (i < n4) {
        float4 v = ((const float4*)src)[i];
        ((uint2*)g_xh)[i] = make_uint2(
            packh(__float2half_rn(v.x), __float2half_rn(v.y)),
            packh(__float2half_rn(v.z), __float2half_rn(v.w)));
    }
}
__global__ void conv_w_kernel(const float* __restrict__ src, int n4) {
    int i = blockIdx.x * blockDim.x + threadIdx.x;
    if (i < n4) {
        float4 v = ((const float4*)src)[i];
        ((uint2*)g_wh)[i] = make_uint2(
            packh(__float2half_rn(v.x), __float2half_rn(v.y)),
            packh(__float2half_rn(v.z), __float2half_rn(v.w)));
    }
}

// ---------------------------------------------------------------------------
// Flash attention: CTA = (q-tile 64, head, batch); 128 threads = 4 warps.
// smem: Q 0..8K; K stages: 8K + s*8K. Total 24KB -> 3 CTAs/SM.
// S = Qh*Kh ;  O += Ph*Vh  (V = K tile).
// ---------------------------------------------------------------------------
__global__ __launch_bounds__(128, 3) void attn_kernel() {
    extern __shared__ __align__(128) char sm[];
    const uint32_t sb = smem_u32(sm);
    const int tid = threadIdx.x, lane = tid & 31, wid = tid >> 5;
    const int qt = blockIdx.x, h = blockIdx.y, b = blockIdx.z;
    const int q0 = qt * BQ;
    const int gID = lane >> 2, tc = lane & 3;

    // Issue K stage-0 cp.async first (overlaps Q setup)
    {
        #pragma unroll
        for (int i = 0; i < 4; i++) {
            int e = i * 128 + tid;        // 0..511
            int row = e >> 3, ch = e & 7;
            size_t src = ((size_t)(b * SEQ + row)) * HID + h * DH + ch * 8;
            cp16(sb + 8192 + SW(row * 128 + ch * 16), g_xh + src);
        }
        CP_COMMIT();
    }

    // Load Q tile (64 rows x 128B)
    #pragma unroll
    for (int i = 0; i < 4; i++) {
        int e = i * 128 + tid;            // 0..511
        int row = e >> 3, ch = e & 7;
        size_t src = ((size_t)(b * SEQ + q0 + row)) * HID + h * DH + ch * 8;
        *(uint4*)(sm + SW(row * 128 + ch * 16)) = *(const uint4*)(g_xh + src);
    }
    __syncthreads();

    // Q fragments (registers, reused across all KV tiles)
    uint32_t aQh[4][4];
    {
        int row = wid * 16 + (lane & 15);
        int chb = lane >> 4;
        #pragma unroll
        for (int ks = 0; ks < 4; ks++) {
            uint32_t o = SW(row * 128 + (ks * 2 + chb) * 16);
            ldm_x4(aQh[ks][0], aQh[ks][1], aQh[ks][2], aQh[ks][3], sb + o);
        }
    }

    float o_[8][4];
    #pragma unroll
    for (int n = 0; n < 8; n++)
        #pragma unroll
        for (int j = 0; j < 4; j++) o_[n][j] = 0.0f;
    float m_lo = -1e30f, m_hi = -1e30f, l_lo = 0.0f, l_hi = 0.0f;

    for (int kt = 0; kt < NT; kt++) {
        const uint32_t kb = 8192 + (uint32_t)(kt & 1) * 8192;  // stage base
        __syncthreads();   // everyone done reading the other stage
        if (kt + 1 < NT) {
            const uint32_t nb = 8192 + (uint32_t)((kt + 1) & 1) * 8192;
            #pragma unroll
            for (int i = 0; i < 4; i++) {
                int e = i * 128 + tid;
                int row = e >> 3, ch = e & 7;
                size_t src = ((size_t)(b * SEQ + (kt + 1) * BK + row)) * HID + h * DH + ch * 8;
                cp16(nb + sb + SW(row * 128 + ch * 16), g_xh + src);
            }
            CP_COMMIT();
            CP_WAIT(1);
        } else {
            CP_WAIT(0);
        }
        __syncthreads();   // stage kb data visible

        // ---- S = Qh K_h^T ----
        float s[8][4];
        #pragma unroll
        for (int n = 0; n < 8; n++)
            #pragma unroll
            for (int j = 0; j < 4; j++) s[n][j] = 0.0f;

        #pragma unroll
        for (int n = 0; n < 8; n++) {
            int row = n * 8 + (lane & 7);
            #pragma unroll
            for (int p = 0; p < 2; p++) {
                uint32_t o = SW(row * 128 + (p * 4 + (lane >> 3)) * 16);
                uint32_t b0, b1, b2, b3;
                ldm_x4(b0, b1, b2, b3, sb + kb + o);
                mma_f16(s[n], aQh[2 * p],     b0, b1);
                mma_f16(s[n], aQh[2 * p + 1], b2, b3);
            }
        }

        // ---- online softmax ----
        const float sc = 0.125f;
        float mlo = -1e30f, mhi = -1e30f;
        #pragma unroll
        for (int n = 0; n < 8; n++) {
            mlo = fmaxf(mlo, fmaxf(s[n][0], s[n][1]));
            mhi = fmaxf(mhi, fmaxf(s[n][2], s[n][3]));
        }
        mlo = fmaxf(mlo, __shfl_xor_sync(0xffffffffu, mlo, 1));
        mlo = fmaxf(mlo, __shfl_xor_sync(0xffffffffu, mlo, 2));
        mhi = fmaxf(mhi, __shfl_xor_sync(0xffffffffu, mhi, 1));
        mhi = fmaxf(mhi, __shfl_xor_sync(0xffffffffu, mhi, 2));
        float nml = fmaxf(m_lo, mlo * sc), nmh = fmaxf(m_hi, mhi * sc);
        float clo = __expf(m_lo - nml), chi = __expf(m_hi - nmh);
        m_lo = nml; m_hi = nmh;

        float slo = 0.0f, shi = 0.0f;
        uint32_t aPh[4][4];
        #pragma unroll
        for (int n = 0; n < 8; n++) {
            float p0 = __expf(s[n][0] * sc - nml);
            float p1 = __expf(s[n][1] * sc - nml);
            float p2 = __expf(s[n][2] * sc - nmh);
            float p3 = __expf(s[n][3] * sc - nmh);
            slo += p0 + p1;
            shi += p2 + p3;
            int t = n >> 1, idx = (n & 1) * 2;
            aPh[t][idx]     = packh(__float2half_rn(p0), __float2half_rn(p1));
            aPh[t][idx + 1] = packh(__float2half_rn(p2), __float2half_rn(p3));
        }
        slo += __shfl_xor_sync(0xffffffffu, slo, 1);
        slo += __shfl_xor_sync(0xffffffffu, slo, 2);
        shi += __shfl_xor_sync(0xffffffffu, shi, 1);
        shi += __shfl_xor_sync(0xffffffffu, shi, 2);
        l_lo = l_lo * clo + slo;
        l_hi = l_hi * chi + shi;
        #pragma unroll
        for (int n = 0; n < 8; n++) {
            o_[n][0] *= clo; o_[n][1] *= clo;
            o_[n][2] *= chi; o_[n][3] *= chi;
        }

        // ---- O += Ph * Vh  (V = K tile; trans ldmatrix) ----
        #pragma unroll
        for (int n = 0; n < 8; n++) {
            #pragma unroll
            for (int p = 0; p < 2; p++) {
                int row = p * 32 + (lane >> 3) * 8 + (lane & 7);
                uint32_t o = SW(row * 128 + n * 16);
                uint32_t v0, v1, v2, v3;
                ldm_x4t(v0, v1, v2, v3, sb + kb + o);
                mma_f16(o_[n], aPh[2 * p],     v0, v1);
                mma_f16(o_[n], aPh[2 * p + 1], v2, v3);
            }
        }
    }

    // ---- normalize, write ctx (fp16) ----
    {
        float il = 1.0f / l_lo, ih = 1.0f / l_hi;
        size_t rlo = (size_t)(b * SEQ + q0 + wid * 16 + gID);
        size_t rhi = rlo + 8;
        #pragma unroll
        for (int n = 0; n < 8; n++) {
            int col = h * DH + n * 8 + tc * 2;
            *(uint32_t*)(g_ch + rlo * HID + col) =
                packh(__float2half_rn(o_[n][0] * il), __float2half_rn(o_[n][1] * il));
            *(uint32_t*)(g_ch + rhi * HID + col) =
                packh(__float2half_rn(o_[n][2] * ih), __float2half_rn(o_[n][3] * ih));
        }
    }
}

// ---------------------------------------------------------------------------
// Projection: out[m][n] = sum_k ctx[m][k] * W[n][k] + bias[n]  (pure fp16 ops)
// 128x128 tile, 256 threads (8 warps 4x2), 2-stage cp.async, 2 CTAs/SM.
// smem per stage: A 0..16K, B 16K..32K. 2 stages = 64KB.
// ---------------------------------------------------------------------------
#define PSTG 32768

__global__ __launch_bounds__(256, 2) void proj_kernel(const float* __restrict__ bias,
                                                      float* __restrict__ out) {
    extern __shared__ __align__(128) char sm[];
    const uint32_t sb = smem_u32(sm);
    const int tid = threadIdx.x, lane = tid & 31, wid = tid >> 5;
    const int wm = wid >> 1, wn = wid & 1;
    const int n0 = blockIdx.x * 128, m0 = blockIdx.y * 128;
    const int gID = lane >> 2, tc = lane & 3;

    float acc[2][8][4];
    #pragma unroll
    for (int mt = 0; mt < 2; mt++)
        #pragma unroll
        for (int n = 0; n < 8; n++)
            #pragma unroll
            for (int j = 0; j < 4; j++) acc[mt][n][j] = 0.0f;

    // prologue: issue kc=0 into stage 0
    {
        #pragma unroll
        for (int i = 0; i < 4; i++) {
            int e = i * 256 + tid;
            int row = e >> 3, ch = e & 7;
            size_t ao = ((size_t)(m0 + row)) * HID + ch * 8;
            size_t bo = ((size_t)(n0 + row)) * HID + ch * 8;
            uint32_t o = SW(row * 128 + ch * 16);
            cp16(sb + o,         g_ch + ao);
            cp16(sb + 16384 + o, g_wh + bo);
        }
        CP_COMMIT();
    }

    for (int kc = 0; kc < HID / 64; kc++) {
        const uint32_t stg = (uint32_t)(kc & 1) * PSTG;
        __syncthreads();
        if (kc + 1 < HID / 64) {
            const uint32_t ns = (uint32_t)((kc + 1) & 1) * PSTG;
            #pragma unroll
            for (int i = 0; i < 4; i++) {
                int e = i * 256 + tid;
                int row = e >> 3, ch = e & 7;
                size_t ao = ((size_t)(m0 + row)) * HID + (kc + 1) * 64 + ch * 8;
                size_t bo = ((size_t)(n0 + row)) * HID + (kc + 1) * 64 + ch * 8;
                uint32_t o = SW(row * 128 + ch * 16);
                cp16(sb + ns + o,         g_ch + ao);
                cp16(sb + ns + 16384 + o, g_wh + bo);
            }
            CP_COMMIT();
            CP_WAIT(1);
        } else {
            CP_WAIT(0);
        }
        __syncthreads();

        #pragma unroll
        for (int p = 0; p < 2; p++) {
            uint32_t aH[2][2][4];
            #pragma unroll
            for (int kk = 0; kk < 2; kk++) {
                int ks = 2 * p + kk;
                #pragma unroll
                for (int mt = 0; mt < 2; mt++) {
                    int row = wm * 32 + mt * 16 + (lane & 15);
                    uint32_t o = SW(row * 128 + (ks * 2 + (lane >> 4)) * 16);
                    ldm_x4(aH[kk][mt][0], aH[kk][mt][1], aH[kk][mt][2], aH[kk][mt][3],
                           sb + stg + o);
                }
            }
            #pragma unroll
            for (int n = 0; n < 8; n++) {
                int row = wn * 64 + n * 8 + (lane & 7);
                uint32_t o = SW(row * 128 + (p * 4 + (lane >> 3)) * 16);
                uint32_t b0, b1, b2, b3;
                ldm_x4(b0, b1, b2, b3, sb + stg + 16384 + o);
                #pragma unroll
                for (int mt = 0; mt < 2; mt++) {
                    mma_f16(acc[mt][n], aH[0][mt], b0, b1);
                    mma_f16(acc[mt][n], aH[1][mt], b2, b3);
                }
            }
        }
    }

    #pragma unroll
    for (int mt = 0; mt < 2; mt++) {
        int rlo = m0 + wm * 32 + mt * 16 + gID;
        #pragma unroll
        for (int n = 0; n < 8; n++) {
            int col = n0 + wn * 64 + n * 8 + tc * 2;
            float b0 = bias[col], b1 = bias[col + 1];
            *(float2*)(out + (size_t)rlo * HID + col) =
                make_float2(acc[mt][n][0] + b0, acc[mt][n][1] + b1);
            *(float2*)(out + (size_t)(rlo + 8) * HID + col) =
                make_float2(acc[mt][n][2] + b0, acc[mt][n][3] + b1);
        }
    }
}

// ---------------------------------------------------------------------------
extern "C" void kernel_launch(void* const* d_in, const int* in_sizes, int n_in,
                              void* d_out, int out_size) {
    const float* x    = (const float*)d_in[0];
    const float* W    = (const float*)d_in[1];
    const float* bias = (const float*)d_in[2];
    float* out = (float*)d_out;

    const int ASM = 24576;          // 8KB Q + 2x8KB K stages
    const int PSM = 2 * PSTG;       // 64KB
    cudaFuncSetAttribute(attn_kernel, cudaFuncAttributeMaxDynamicSharedMemorySize, ASM);
    cudaFuncSetAttribute(proj_kernel, cudaFuncAttributeMaxDynamicSharedMemorySize, PSM);

    const int nx4 = (BATCH * SEQ * HID) / 4;
    const int nw4 = (HID * HID) / 4;
    conv_x_kernel<<<(nx4 + 255) / 256, 256>>>(x, nx4);
    conv_w_kernel<<<(nw4 + 255) / 256, 256>>>(W, nw4);

    dim3 g1(SEQ / BQ, NH, BATCH);              // (32,16,2) = 1024 CTAs
    attn_kernel<<<g1, 128, ASM>>>();

    dim3 g2(HID / 128, (BATCH * SEQ) / 128);   // (8,32) = 256 CTAs
    proj_kernel<<<g2, 256, PSM>>>(bias, out);
}

// round 8
// speedup vs baseline: 14.5162x; 1.1462x over previous
#include <cuda_runtime.h>
#include <cuda_fp16.h>
#include <stdint.h>

#define BATCH 2
#define SEQ   2048
#define HID   1024
#define NH    16
#define DH    64
#define BQ    64
#define BK    64
#define NT    (SEQ / BK)

// fp16 casts in global scratch
__device__ __half g_xh[(size_t)BATCH * SEQ * HID];   // fp16(x)            (K/V side)
__device__ __half g_xq[(size_t)BATCH * SEQ * HID];   // fp16(x * 0.125*log2e)  (Q side)
__device__ __half g_ch[(size_t)BATCH * SEQ * HID];   // fp16(ctx)
__device__ __half g_wh[(size_t)HID * HID];           // fp16(W)

#define QSCALE 0.1803368801111204f   // 0.125 * log2(e)

// ---------------------------------------------------------------------------
__device__ __forceinline__ uint32_t smem_u32(const void* p) {
    uint32_t a;
    asm("{ .reg .u64 t; cvta.to.shared.u64 t, %1; cvt.u32.u64 %0, t; }" : "=r"(a) : "l"(p));
    return a;
}

#define SW(o) ((uint32_t)(o) ^ ((((uint32_t)(o)) >> 3) & 0x70))

__device__ __forceinline__ void ldm_x4(uint32_t& r0, uint32_t& r1, uint32_t& r2, uint32_t& r3,
                                       uint32_t addr) {
    asm volatile("ldmatrix.sync.aligned.m8n8.x4.shared.b16 {%0,%1,%2,%3}, [%4];"
                 : "=r"(r0), "=r"(r1), "=r"(r2), "=r"(r3) : "r"(addr));
}
__device__ __forceinline__ void ldm_x4t(uint32_t& r0, uint32_t& r1, uint32_t& r2, uint32_t& r3,
                                        uint32_t addr) {
    asm volatile("ldmatrix.sync.aligned.m8n8.x4.trans.shared.b16 {%0,%1,%2,%3}, [%4];"
                 : "=r"(r0), "=r"(r1), "=r"(r2), "=r"(r3) : "r"(addr));
}

__device__ __forceinline__ void mma_f16(float* c, const uint32_t* a, uint32_t b0, uint32_t b1) {
    asm volatile("mma.sync.aligned.m16n8k16.row.col.f32.f16.f16.f32 "
                 "{%0,%1,%2,%3}, {%4,%5,%6,%7}, {%8,%9}, {%0,%1,%2,%3};"
                 : "+f"(c[0]), "+f"(c[1]), "+f"(c[2]), "+f"(c[3])
                 : "r"(a[0]), "r"(a[1]), "r"(a[2]), "r"(a[3]), "r"(b0), "r"(b1));
}

__device__ __forceinline__ void cp16(uint32_t dst, const void* src) {
    asm volatile("cp.async.cg.shared.global [%0], [%1], 16;" :: "r"(dst), "l"(src));
}
#define CP_COMMIT() asm volatile("cp.async.commit_group;" ::: "memory")
#define CP_WAIT(n)  asm volatile("cp.async.wait_group %0;" :: "n"(n) : "memory")

__device__ __forceinline__ float ex2(float x) {
    float y;
    asm("ex2.approx.ftz.f32 %0, %1;" : "=f"(y) : "f"(x));
    return y;
}

__device__ __forceinline__ uint32_t packf2(float lo, float hi) {
    __half2 h = __float22half2_rn(make_float2(lo, hi));
    return *(uint32_t*)&h;
}
__device__ __forceinline__ uint32_t packh(__half lo, __half hi) {
    return (uint32_t)__half_as_ushort(lo) | ((uint32_t)__half_as_ushort(hi) << 16);
}

// ---------------------------------------------------------------------------
// Combined convert: [0, nx4) -> x (g_xh + scaled g_xq); [nx4, nx4+nw4) -> W.
// ---------------------------------------------------------------------------
__global__ void conv_kernel(const float* __restrict__ x, const float* __restrict__ W,
                            int nx4, int nw4) {
    int i = blockIdx.x * blockDim.x + threadIdx.x;
    if (i < nx4) {
        float4 v = ((const float4*)x)[i];
        ((uint2*)g_xh)[i] = make_uint2(
            packh(__float2half_rn(v.x), __float2half_rn(v.y)),
            packh(__float2half_rn(v.z), __float2half_rn(v.w)));
        ((uint2*)g_xq)[i] = make_uint2(
            packf2(v.x * QSCALE, v.y * QSCALE),
            packf2(v.z * QSCALE, v.w * QSCALE));
    } else if (i < nx4 + nw4) {
        int j = i - nx4;
        float4 v = ((const float4*)W)[j];
        ((uint2*)g_wh)[j] = make_uint2(
            packh(__float2half_rn(v.x), __float2half_rn(v.y)),
            packh(__float2half_rn(v.z), __float2half_rn(v.w)));
    }
}

// ---------------------------------------------------------------------------
// Flash attention: CTA = (q-tile 64, head, batch); 128 threads = 4 warps.
// smem: Q 0..8K; K stages: 8K + s*8K. Total 24KB -> 3 CTAs/SM.
// S (base-2 pre-scaled) = Qs*Kh ;  O += Ph*Vh  (V = K tile).
// ---------------------------------------------------------------------------
__global__ __launch_bounds__(128, 3) void attn_kernel() {
    extern __shared__ __align__(128) char sm[];
    const uint32_t sb = smem_u32(sm);
    const int tid = threadIdx.x, lane = tid & 31, wid = tid >> 5;
    const int qt = blockIdx.x, h = blockIdx.y, b = blockIdx.z;
    const int q0 = qt * BQ;
    const int gID = lane >> 2, tc = lane & 3;

    // Issue K stage-0 cp.async first (overlaps Q setup)
    {
        #pragma unroll
        for (int i = 0; i < 4; i++) {
            int e = i * 128 + tid;        // 0..511
            int row = e >> 3, ch = e & 7;
            size_t src = ((size_t)(b * SEQ + row)) * HID + h * DH + ch * 8;
            cp16(sb + 8192 + SW(row * 128 + ch * 16), g_xh + src);
        }
        CP_COMMIT();
    }

    // Load Q tile (scaled variant; 64 rows x 128B)
    #pragma unroll
    for (int i = 0; i < 4; i++) {
        int e = i * 128 + tid;            // 0..511
        int row = e >> 3, ch = e & 7;
        size_t src = ((size_t)(b * SEQ + q0 + row)) * HID + h * DH + ch * 8;
        *(uint4*)(sm + SW(row * 128 + ch * 16)) = *(const uint4*)(g_xq + src);
    }
    __syncthreads();

    // Q fragments (registers, reused across all KV tiles)
    uint32_t aQh[4][4];
    {
        int row = wid * 16 + (lane & 15);
        int chb = lane >> 4;
        #pragma unroll
        for (int ks = 0; ks < 4; ks++) {
            uint32_t o = SW(row * 128 + (ks * 2 + chb) * 16);
            ldm_x4(aQh[ks][0], aQh[ks][1], aQh[ks][2], aQh[ks][3], sb + o);
        }
    }

    float o_[8][4];
    #pragma unroll
    for (int n = 0; n < 8; n++)
        #pragma unroll
        for (int j = 0; j < 4; j++) o_[n][j] = 0.0f;
    float m_lo = -1e30f, m_hi = -1e30f, l_lo = 0.0f, l_hi = 0.0f;

    for (int kt = 0; kt < NT; kt++) {
        const uint32_t kb = 8192 + (uint32_t)(kt & 1) * 8192;  // stage base
        __syncthreads();   // everyone done reading the other stage
        if (kt + 1 < NT) {
            const uint32_t nb = 8192 + (uint32_t)((kt + 1) & 1) * 8192;
            #pragma unroll
            for (int i = 0; i < 4; i++) {
                int e = i * 128 + tid;
                int row = e >> 3, ch = e & 7;
                size_t src = ((size_t)(b * SEQ + (kt + 1) * BK + row)) * HID + h * DH + ch * 8;
                cp16(nb + sb + SW(row * 128 + ch * 16), g_xh + src);
            }
            CP_COMMIT();
            CP_WAIT(1);
        } else {
            CP_WAIT(0);
        }
        __syncthreads();   // stage kb data visible

        // ---- S = Qs K^T  (scores already in base-2 units) ----
        float s[8][4];
        #pragma unroll
        for (int n = 0; n < 8; n++)
            #pragma unroll
            for (int j = 0; j < 4; j++) s[n][j] = 0.0f;

        #pragma unroll
        for (int n = 0; n < 8; n++) {
            int row = n * 8 + (lane & 7);
            #pragma unroll
            for (int p = 0; p < 2; p++) {
                uint32_t o = SW(row * 128 + (p * 4 + (lane >> 3)) * 16);
                uint32_t b0, b1, b2, b3;
                ldm_x4(b0, b1, b2, b3, sb + kb + o);
                mma_f16(s[n], aQh[2 * p],     b0, b1);
                mma_f16(s[n], aQh[2 * p + 1], b2, b3);
            }
        }

        // ---- online softmax (base 2, lazy rescale, deferred l reduce) ----
        float mlo = -1e30f, mhi = -1e30f;
        #pragma unroll
        for (int n = 0; n < 8; n++) {
            mlo = fmaxf(mlo, fmaxf(s[n][0], s[n][1]));
            mhi = fmaxf(mhi, fmaxf(s[n][2], s[n][3]));
        }
        mlo = fmaxf(mlo, __shfl_xor_sync(0xffffffffu, mlo, 1));
        mlo = fmaxf(mlo, __shfl_xor_sync(0xffffffffu, mlo, 2));
        mhi = fmaxf(mhi, __shfl_xor_sync(0xffffffffu, mhi, 1));
        mhi = fmaxf(mhi, __shfl_xor_sync(0xffffffffu, mhi, 2));

        if (mlo > m_lo) {
            float clo = ex2(m_lo - mlo);
            m_lo = mlo;
            l_lo *= clo;
            #pragma unroll
            for (int n = 0; n < 8; n++) { o_[n][0] *= clo; o_[n][1] *= clo; }
        }
        if (mhi > m_hi) {
            float chi = ex2(m_hi - mhi);
            m_hi = mhi;
            l_hi *= chi;
            #pragma unroll
            for (int n = 0; n < 8; n++) { o_[n][2] *= chi; o_[n][3] *= chi; }
        }

        float slo = 0.0f, shi = 0.0f;
        uint32_t aPh[4][4];
        #pragma unroll
        for (int n = 0; n < 8; n++) {
            float p0 = ex2(s[n][0] - m_lo);
            float p1 = ex2(s[n][1] - m_lo);
            float p2 = ex2(s[n][2] - m_hi);
            float p3 = ex2(s[n][3] - m_hi);
            slo += p0 + p1;
            shi += p2 + p3;
            int t = n >> 1, idx = (n & 1) * 2;
            aPh[t][idx]     = packf2(p0, p1);
            aPh[t][idx + 1] = packf2(p2, p3);
        }
        l_lo += slo;   // per-thread partial; quad-reduced at the end
        l_hi += shi;

        // ---- O += Ph * Vh  (V = K tile; trans ldmatrix) ----
        #pragma unroll
        for (int n = 0; n < 8; n++) {
            #pragma unroll
            for (int p = 0; p < 2; p++) {
                int row = p * 32 + (lane >> 3) * 8 + (lane & 7);
                uint32_t o = SW(row * 128 + n * 16);
                uint32_t v0, v1, v2, v3;
                ldm_x4t(v0, v1, v2, v3, sb + kb + o);
                mma_f16(o_[n], aPh[2 * p],     v0, v1);
                mma_f16(o_[n], aPh[2 * p + 1], v2, v3);
            }
        }
    }

    // ---- final l reduction across the quad, normalize, write ctx ----
    l_lo += __shfl_xor_sync(0xffffffffu, l_lo, 1);
    l_lo += __shfl_xor_sync(0xffffffffu, l_lo, 2);
    l_hi += __shfl_xor_sync(0xffffffffu, l_hi, 1);
    l_hi += __shfl_xor_sync(0xffffffffu, l_hi, 2);
    {
        float il = 1.0f / l_lo, ih = 1.0f / l_hi;
        size_t rlo = (size_t)(b * SEQ + q0 + wid * 16 + gID);
        size_t rhi = rlo + 8;
        #pragma unroll
        for (int n = 0; n < 8; n++) {
            int col = h * DH + n * 8 + tc * 2;
            *(uint32_t*)(g_ch + rlo * HID + col) = packf2(o_[n][0] * il, o_[n][1] * il);
            *(uint32_t*)(g_ch + rhi * HID + col) = packf2(o_[n][2] * ih, o_[n][3] * ih);
        }
    }
}

// ---------------------------------------------------------------------------
// Projection: out[m][n] = sum_k ctx[m][k] * W[n][k] + bias[n]  (pure fp16 ops)
// 128x128 tile, 256 threads (8 warps 4x2), 2-stage cp.async, 2 CTAs/SM.
// smem per stage: A 0..16K, B 16K..32K. 2 stages = 64KB.
// ---------------------------------------------------------------------------
#define PSTG 32768

__global__ __launch_bounds__(256, 2) void proj_kernel(const float* __restrict__ bias,
                                                      float* __restrict__ out) {
    extern __shared__ __align__(128) char sm[];
    const uint32_t sb = smem_u32(sm);
    const int tid = threadIdx.x, lane = tid & 31, wid = tid >> 5;
    const int wm = wid >> 1, wn = wid & 1;
    const int n0 = blockIdx.x * 128, m0 = blockIdx.y * 128;
    const int gID = lane >> 2, tc = lane & 3;

    float acc[2][8][4];
    #pragma unroll
    for (int mt = 0; mt < 2; mt++)
        #pragma unroll
        for (int n = 0; n < 8; n++)
            #pragma unroll
            for (int j = 0; j < 4; j++) acc[mt][n][j] = 0.0f;

    // prologue: issue kc=0 into stage 0
    {
        #pragma unroll
        for (int i = 0; i < 4; i++) {
            int e = i * 256 + tid;
            int row = e >> 3, ch = e & 7;
            size_t ao = ((size_t)(m0 + row)) * HID + ch * 8;
            size_t bo = ((size_t)(n0 + row)) * HID + ch * 8;
            uint32_t o = SW(row * 128 + ch * 16);
            cp16(sb + o,         g_ch + ao);
            cp16(sb + 16384 + o, g_wh + bo);
        }
        CP_COMMIT();
    }

    for (int kc = 0; kc < HID / 64; kc++) {
        const uint32_t stg = (uint32_t)(kc & 1) * PSTG;
        __syncthreads();
        if (kc + 1 < HID / 64) {
            const uint32_t ns = (uint32_t)((kc + 1) & 1) * PSTG;
            #pragma unroll
            for (int i = 0; i < 4; i++) {
                int e = i * 256 + tid;
                int row = e >> 3, ch = e & 7;
                size_t ao = ((size_t)(m0 + row)) * HID + (kc + 1) * 64 + ch * 8;
                size_t bo = ((size_t)(n0 + row)) * HID + (kc + 1) * 64 + ch * 8;
                uint32_t o = SW(row * 128 + ch * 16);
                cp16(sb + ns + o,         g_ch + ao);
                cp16(sb + ns + 16384 + o, g_wh + bo);
            }
            CP_COMMIT();
            CP_WAIT(1);
        } else {
            CP_WAIT(0);
        }
        __syncthreads();

        #pragma unroll
        for (int p = 0; p < 2; p++) {
            uint32_t aH[2][2][4];
            #pragma unroll
            for (int kk = 0; kk < 2; kk++) {
                int ks = 2 * p + kk;
                #pragma unroll
                for (int mt = 0; mt < 2; mt++) {
                    int row = wm * 32 + mt * 16 + (lane & 15);
                    uint32_t o = SW(row * 128 + (ks * 2 + (lane >> 4)) * 16);
                    ldm_x4(aH[kk][mt][0], aH[kk][mt][1], aH[kk][mt][2], aH[kk][mt][3],
                           sb + stg + o);
                }
            }
            #pragma unroll
            for (int n = 0; n < 8; n++) {
                int row = wn * 64 + n * 8 + (lane & 7);
                uint32_t o = SW(row * 128 + (p * 4 + (lane >> 3)) * 16);
                uint32_t b0, b1, b2, b3;
                ldm_x4(b0, b1, b2, b3, sb + stg + 16384 + o);
                #pragma unroll
                for (int mt = 0; mt < 2; mt++) {
                    mma_f16(acc[mt][n], aH[0][mt], b0, b1);
                    mma_f16(acc[mt][n], aH[1][mt], b2, b3);
                }
            }
        }
    }

    #pragma unroll
    for (int mt = 0; mt < 2; mt++) {
        int rlo = m0 + wm * 32 + mt * 16 + gID;
        #pragma unroll
        for (int n = 0; n < 8; n++) {
            int col = n0 + wn * 64 + n * 8 + tc * 2;
            float b0 = bias[col], b1 = bias[col + 1];
            *(float2*)(out + (size_t)rlo * HID + col) =
                make_float2(acc[mt][n][0] + b0, acc[mt][n][1] + b1);
            *(float2*)(out + (size_t)(rlo + 8) * HID + col) =
                make_float2(acc[mt][n][2] + b0, acc[mt][n][3] + b1);
        }
    }
}

// ---------------------------------------------------------------------------
extern "C" void kernel_launch(void* const* d_in, const int* in_sizes, int n_in,
                              void* d_out, int out_size) {
    const float* x    = (const float*)d_in[0];
    const float* W    = (const float*)d_in[1];
    const float* bias = (const float*)d_in[2];
    float* out = (float*)d_out;

    const int ASM = 24576;          // 8KB Q + 2x8KB K stages
    const int PSM = 2 * PSTG;       // 64KB
    cudaFuncSetAttribute(attn_kernel, cudaFuncAttributeMaxDynamicSharedMemorySize, ASM);
    cudaFuncSetAttribute(proj_kernel, cudaFuncAttributeMaxDynamicSharedMemorySize, PSM);

    const int nx4 = (BATCH * SEQ * HID) / 4;
    const int nw4 = (HID * HID) / 4;
    conv_kernel<<<(nx4 + nw4 + 255) / 256, 256>>>(x, W, nx4, nw4);

    dim3 g1(SEQ / BQ, NH, BATCH);              // (32,16,2) = 1024 CTAs
    attn_kernel<<<g1, 128, ASM>>>();

    dim3 g2(HID / 128, (BATCH * SEQ) / 128);   // (8,32) = 256 CTAs
    proj_kernel<<<g2, 256, PSM>>>(bias, out);
}